// round 3
// baseline (speedup 1.0000x reference)
#include <cuda_runtime.h>

// Problem constants
#define B_ROWS 65536
#define J_DOM  8
#define D0 512
#define H0 256
#define H1 128
#define H2 64

// -------- device scratch (static globals; no runtime allocation) --------
__device__ float g_w0[J_DOM * D0 * H0];                 // 4 MB
__device__ float g_w1[J_DOM * H0 * H1];                 // 1 MB
__device__ float g_w2[J_DOM * H1 * H2];                 // 256 KB
__device__ float g_h0[(size_t)J_DOM * B_ROWS * H0];     // 512 MB  [J][B][H0]
__device__ float g_h1[(size_t)J_DOM * B_ROWS * H1];     // 256 MB  [J][B][H1]

// -------- weight fusion: w[j,i,o] = sk[i,o] * dk[j,i,o] --------
__global__ void fuse_weights(const float* __restrict__ sk,
                             const float* __restrict__ dk,
                             float* __restrict__ w, int IO, int total) {
    int i = blockIdx.x * blockDim.x + threadIdx.x;
    if (i < total) w[i] = sk[i % IO] * dk[i];
}

// -------- batched GEMM + bias + relu --------
// C[j][m][n] = relu( A[j][m][:] @ W[j][:][n] + sb[n] + db[j][n] )
// Tiles: 128x128, K-tile 8, 256 threads, 8x8 per thread.
__global__ void __launch_bounds__(256, 2) gemm_relu(
    const float* __restrict__ A, int lda, size_t a_jstride,
    const float* __restrict__ W,
    const float* __restrict__ sb, const float* __restrict__ db,
    float* __restrict__ C, int K, int N)
{
    const int j  = blockIdx.z;
    const int m0 = blockIdx.x * 128;
    const int n0 = blockIdx.y * 128;

    const float* Aj  = A + (size_t)j * a_jstride;
    const float* Wj  = W + (size_t)j * K * N;
    const float* dbj = db + j * N;
    float*       Cj  = C + (size_t)j * B_ROWS * N;

    __shared__ float As[8][128];
    __shared__ float Bs[8][128];

    const int tid = threadIdx.x;
    const int tx  = tid & 15;     // 16 col groups * 8
    const int ty  = tid >> 4;     // 16 row groups * 8

    const int arow = tid >> 1;
    const int acol = (tid & 1) * 4;
    const int brow = tid >> 5;
    const int bcol = (tid & 31) * 4;

    const float* Aptr = Aj + (size_t)(m0 + arow) * lda + acol;
    const float* Bptr = Wj + (size_t)brow * N + n0 + bcol;

    float acc[8][8];
#pragma unroll
    for (int i = 0; i < 8; i++)
#pragma unroll
        for (int n = 0; n < 8; n++) acc[i][n] = 0.f;

    float4 av = *(const float4*)(Aptr);
    float4 bv = *(const float4*)(Bptr);

    for (int k0 = 0; k0 < K; k0 += 8) {
        __syncthreads();
        As[acol + 0][arow] = av.x;
        As[acol + 1][arow] = av.y;
        As[acol + 2][arow] = av.z;
        As[acol + 3][arow] = av.w;
        *(float4*)&Bs[brow][bcol] = bv;
        __syncthreads();
        if (k0 + 8 < K) {   // prefetch next k-tile while computing this one
            av = *(const float4*)(Aptr + k0 + 8);
            bv = *(const float4*)(Bptr + (size_t)(k0 + 8) * N);
        }
#pragma unroll
        for (int kk = 0; kk < 8; kk++) {
            float4 a0 = *(const float4*)&As[kk][ty * 8];
            float4 a1 = *(const float4*)&As[kk][ty * 8 + 4];
            float4 b0 = *(const float4*)&Bs[kk][tx * 8];
            float4 b1 = *(const float4*)&Bs[kk][tx * 8 + 4];
            float a[8] = {a0.x, a0.y, a0.z, a0.w, a1.x, a1.y, a1.z, a1.w};
            float b[8] = {b0.x, b0.y, b0.z, b0.w, b1.x, b1.y, b1.z, b1.w};
#pragma unroll
            for (int i = 0; i < 8; i++)
#pragma unroll
                for (int n = 0; n < 8; n++)
                    acc[i][n] = fmaf(a[i], b[n], acc[i][n]);
        }
    }

#pragma unroll
    for (int i = 0; i < 8; i++) {
        const int m = m0 + ty * 8 + i;
        float* crow = Cj + (size_t)m * N + n0 + tx * 8;
#pragma unroll
        for (int h = 0; h < 2; h++) {
            const int nb = n0 + tx * 8 + h * 4;
            float4 v;
            v.x = fmaxf(acc[i][h * 4 + 0] + sb[nb + 0] + dbj[nb + 0], 0.f);
            v.y = fmaxf(acc[i][h * 4 + 1] + sb[nb + 1] + dbj[nb + 1], 0.f);
            v.z = fmaxf(acc[i][h * 4 + 2] + sb[nb + 2] + dbj[nb + 2], 0.f);
            v.w = fmaxf(acc[i][h * 4 + 3] + sb[nb + 3] + dbj[nb + 3], 0.f);
            *(float4*)(crow + h * 4) = v;
        }
    }
}

// -------- layer 2 + domain mix, fused --------
// out[m][n] = sum_j ind[m][j] * relu( H1[j][m][:] @ W2[j][:][n] + sb2[n] + db2[j][n] )
// Tile 128x64, K=128, loops j in-block (deterministic, no atomics).
__global__ void __launch_bounds__(256, 2) l2_mix(
    const float* __restrict__ Hin, const float* __restrict__ W2,
    const float* __restrict__ sb2, const float* __restrict__ db2,
    const float* __restrict__ ind, float* __restrict__ out)
{
    const int m0 = blockIdx.x * 128;

    __shared__ float As[8][128];
    __shared__ float Bs[8][64];
    __shared__ float inds[128][9];   // padded to kill bank conflicts

    const int tid = threadIdx.x;
    const int tx  = tid & 15;     // 16 * 4 cols
    const int ty  = tid >> 4;     // 16 * 8 rows

    for (int idx = tid; idx < 128 * 8; idx += 256) {
        int r = idx >> 3, c = idx & 7;
        inds[r][c] = ind[(size_t)(m0 + r) * 8 + c];
    }

    const int arow = tid >> 1;
    const int acol = (tid & 1) * 4;
    const int brow = tid >> 5;
    const int bcol = (tid & 31) * 2;

    float accf[8][4];
#pragma unroll
    for (int i = 0; i < 8; i++)
#pragma unroll
        for (int n = 0; n < 4; n++) accf[i][n] = 0.f;

    for (int j = 0; j < J_DOM; j++) {
        const float* Aptr = Hin + ((size_t)j * B_ROWS + m0 + arow) * H1 + acol;
        const float* Bptr = W2 + (size_t)j * H1 * H2 + (size_t)brow * H2 + bcol;

        float acc[8][4];
#pragma unroll
        for (int i = 0; i < 8; i++)
#pragma unroll
            for (int n = 0; n < 4; n++) acc[i][n] = 0.f;

        for (int k0 = 0; k0 < H1; k0 += 8) {
            float4 av = *(const float4*)(Aptr + k0);
            float2 bv = *(const float2*)(Bptr + (size_t)k0 * H2);
            __syncthreads();
            As[acol + 0][arow] = av.x;
            As[acol + 1][arow] = av.y;
            As[acol + 2][arow] = av.z;
            As[acol + 3][arow] = av.w;
            Bs[brow][bcol]     = bv.x;
            Bs[brow][bcol + 1] = bv.y;
            __syncthreads();
#pragma unroll
            for (int kk = 0; kk < 8; kk++) {
                float4 a0 = *(const float4*)&As[kk][ty * 8];
                float4 a1 = *(const float4*)&As[kk][ty * 8 + 4];
                float4 b  = *(const float4*)&Bs[kk][tx * 4];
                float a[8] = {a0.x, a0.y, a0.z, a0.w, a1.x, a1.y, a1.z, a1.w};
                float bb[4] = {b.x, b.y, b.z, b.w};
#pragma unroll
                for (int i = 0; i < 8; i++)
#pragma unroll
                    for (int n = 0; n < 4; n++)
                        acc[i][n] = fmaf(a[i], bb[n], acc[i][n]);
            }
        }

        const float* db2j = db2 + j * H2;
#pragma unroll
        for (int i = 0; i < 8; i++) {
            float s = inds[ty * 8 + i][j];
#pragma unroll
            for (int n = 0; n < 4; n++) {
                int ng = tx * 4 + n;
                float v = fmaxf(acc[i][n] + sb2[ng] + db2j[ng], 0.f);
                accf[i][n] = fmaf(s, v, accf[i][n]);
            }
        }
    }

#pragma unroll
    for (int i = 0; i < 8; i++) {
        float4 v = {accf[i][0], accf[i][1], accf[i][2], accf[i][3]};
        *(float4*)(out + (size_t)(m0 + ty * 8 + i) * H2 + tx * 4) = v;
    }
}

extern "C" void kernel_launch(void* const* d_in, const int* in_sizes, int n_in,
                              void* d_out, int out_size) {
    const float* x   = (const float*)d_in[0];
    const float* ind = (const float*)d_in[1];
    const float* sk0 = (const float*)d_in[2];
    const float* sb0 = (const float*)d_in[3];
    const float* dk0 = (const float*)d_in[4];
    const float* db0 = (const float*)d_in[5];
    const float* sk1 = (const float*)d_in[6];
    const float* sb1 = (const float*)d_in[7];
    const float* dk1 = (const float*)d_in[8];
    const float* db1 = (const float*)d_in[9];
    const float* sk2 = (const float*)d_in[10];
    const float* sb2 = (const float*)d_in[11];
    const float* dk2 = (const float*)d_in[12];
    const float* db2 = (const float*)d_in[13];
    float* out = (float*)d_out;

    float *w0, *w1, *w2, *h0, *h1;
    cudaGetSymbolAddress((void**)&w0, g_w0);
    cudaGetSymbolAddress((void**)&w1, g_w1);
    cudaGetSymbolAddress((void**)&w2, g_w2);
    cudaGetSymbolAddress((void**)&h0, g_h0);
    cudaGetSymbolAddress((void**)&h1, g_h1);

    {
        int t0 = J_DOM * D0 * H0;
        int t1 = J_DOM * H0 * H1;
        int t2 = J_DOM * H1 * H2;
        fuse_weights<<<(t0 + 255) / 256, 256>>>(sk0, dk0, w0, D0 * H0, t0);
        fuse_weights<<<(t1 + 255) / 256, 256>>>(sk1, dk1, w1, H0 * H1, t1);
        fuse_weights<<<(t2 + 255) / 256, 256>>>(sk2, dk2, w2, H1 * H2, t2);
    }

    // layer 0: A = x (shared across j), K=512, N=256 per domain
    gemm_relu<<<dim3(B_ROWS / 128, H0 / 128, J_DOM), 256>>>(
        x, D0, (size_t)0, w0, sb0, db0, h0, D0, H0);

    // layer 1: A = h0[j], K=256, N=128
    gemm_relu<<<dim3(B_ROWS / 128, H1 / 128, J_DOM), 256>>>(
        h0, H0, (size_t)B_ROWS * H0, w1, sb1, db1, h1, H0, H1);

    // layer 2 + domain mix
    l2_mix<<<B_ROWS / 128, 256>>>(h1, w2, sb2, db2, ind, out);
}

// round 7
// speedup vs baseline: 2.2152x; 2.2152x over previous
#include <cuda_runtime.h>
#include <cuda_bf16.h>
#include <cstdint>

// Problem constants
#define B_ROWS 65536
#define J_DOM  8
#define D0 512
#define H0 256
#define H1 128
#define H2 64

typedef __nv_bfloat16 bf16;

// ---------------------------------------------------------------------------
// baseline-PTX helpers (no 'a'-gated features: HMMA mma.sync + ldmatrix + cp.async)
// ---------------------------------------------------------------------------
__device__ __forceinline__ uint32_t smem_to_u32(const void* p) {
    uint32_t a;
    asm("{ .reg .u64 t; cvta.to.shared.u64 t, %1; cvt.u32.u64 %0, t; }" : "=r"(a) : "l"(p));
    return a;
}
__device__ __forceinline__ void ldsm_x4(uint32_t* r, uint32_t addr) {
    asm volatile("ldmatrix.sync.aligned.m8n8.x4.shared.b16 {%0,%1,%2,%3}, [%4];"
                 : "=r"(r[0]), "=r"(r[1]), "=r"(r[2]), "=r"(r[3]) : "r"(addr));
}
__device__ __forceinline__ void mma16816(float* c, const uint32_t* a, const uint32_t* b) {
    asm volatile(
        "mma.sync.aligned.m16n8k16.row.col.f32.bf16.bf16.f32 "
        "{%0,%1,%2,%3}, {%4,%5,%6,%7}, {%8,%9}, {%0,%1,%2,%3};"
        : "+f"(c[0]), "+f"(c[1]), "+f"(c[2]), "+f"(c[3])
        : "r"(a[0]), "r"(a[1]), "r"(a[2]), "r"(a[3]), "r"(b[0]), "r"(b[1]));
}
__device__ __forceinline__ void cp16(uint32_t sm, const void* g) {
    asm volatile("cp.async.cg.shared.global [%0], [%1], 16;" :: "r"(sm), "l"(g));
}
#define CP_COMMIT() asm volatile("cp.async.commit_group;" ::: "memory")
#define CP_WAIT(n)  asm volatile("cp.async.wait_group %0;" :: "n"(n) : "memory")

// swizzled byte offset within a [rows x 64 bf16] tile (128B rows, 16B chunks)
__device__ __forceinline__ int swz(int row, int c) {
    return row * 128 + ((c ^ (row & 7)) << 4);
}

// ---------------------------------------------------------------------------
// Device scratch (static globals; no runtime allocation)
// ---------------------------------------------------------------------------
__device__ bf16 g_xhi[(size_t)B_ROWS * D0];
__device__ bf16 g_xlo[(size_t)B_ROWS * D0];
__device__ bf16 g_w0hi[J_DOM * D0 * H0];     // [J][N][K]
__device__ bf16 g_w0lo[J_DOM * D0 * H0];
__device__ bf16 g_w1hi[J_DOM * H0 * H1];
__device__ bf16 g_w1lo[J_DOM * H0 * H1];
__device__ bf16 g_w2hi[J_DOM * H1 * H2];
__device__ bf16 g_w2lo[J_DOM * H1 * H2];
__device__ bf16 g_h0hi[(size_t)J_DOM * B_ROWS * H0];
__device__ bf16 g_h0lo[(size_t)J_DOM * B_ROWS * H0];
__device__ bf16 g_h1hi[(size_t)J_DOM * B_ROWS * H1];
__device__ bf16 g_h1lo[(size_t)J_DOM * B_ROWS * H1];
__device__ float g_h2[(size_t)J_DOM * B_ROWS * H2];

// ---------------------------------------------------------------------------
// fp32 -> bf16 hi/lo split (x)
// ---------------------------------------------------------------------------
__global__ void conv_split(const float* __restrict__ x, bf16* __restrict__ hi,
                           bf16* __restrict__ lo, size_t total) {
    size_t i = (size_t)blockIdx.x * blockDim.x + threadIdx.x;
    if (i < total) {
        float v = x[i];
        bf16 h = __float2bfloat16(v);
        hi[i] = h;
        lo[i] = __float2bfloat16(v - __bfloat162float(h));
    }
}

// fuse w[j,k,n]=sk[k,n]*dk[j,k,n]; store transposed [j][n][k] hi/lo
__global__ void fuse_wT(const float* __restrict__ sk, const float* __restrict__ dk,
                        bf16* __restrict__ whi, bf16* __restrict__ wlo,
                        int K, int N, int total) {
    int i = blockIdx.x * blockDim.x + threadIdx.x;
    if (i < total) {
        int r = i % (K * N);
        int j = i / (K * N);
        int k = r / N, n = r % N;
        float v = sk[r] * dk[i];
        bf16 h = __float2bfloat16(v);
        size_t o = (size_t)j * K * N + (size_t)n * K + k;
        whi[o] = h;
        wlo[o] = __float2bfloat16(v - __bfloat162float(h));
    }
}

// async tile loader: [ROWS x 64 bf16] K-major -> swizzled SMEM
template<int ROWS>
__device__ __forceinline__ void load_tile(const bf16* __restrict__ src, int pitch,
                                          uint32_t dst, int tid) {
#pragma unroll
    for (int it = 0; it < ROWS / 32; it++) {
        int idx = tid + it * 256;
        int row = idx >> 3, c = idx & 7;
        cp16(dst + swz(row, c), src + (size_t)row * pitch + c * 8);
    }
}

// ---------------------------------------------------------------------------
// HMMA split-bf16 GEMM:  C[j][m][n0+:NT] = act( A[j][m][:] @ W[j][n][:]^T + bias )
// 3 passes (AhBh + AhBl + AlBh) accumulated in fp32 fragments.
// CTA: 256 thr, tile 128 x NT, K chunks of 64, cp.async double buffer.
// ---------------------------------------------------------------------------
template<int NT, bool FP32OUT>
__global__ void __launch_bounds__(256, 1) gemm_hmma(
    const bf16* __restrict__ Ahi, const bf16* __restrict__ Alo,
    size_t a_jstride, int lda,
    const bf16* __restrict__ Whi, const bf16* __restrict__ Wlo,
    const float* __restrict__ sb, const float* __restrict__ db,
    bf16* __restrict__ outHi, bf16* __restrict__ outLo, float* __restrict__ outF,
    int K, int NOUT)
{
    extern __shared__ char smem[];
    const int tid = threadIdx.x, lane = tid & 31, wid = tid >> 5;
    const int j  = blockIdx.x;             // j fastest -> L2 reuse of A tiles
    const int m0 = blockIdx.y * 128;
    const int n0 = blockIdx.z * NT;

    constexpr int ABYTES = 128 * 128;      // one A (hi or lo) chunk tile
    constexpr int BBYTES = NT * 128;
    constexpr int BUF = 2 * ABYTES + 2 * BBYTES;
    constexpr int NSUB = NT / 16;          // n-subtile pairs per warp = NSUB/... per warp NT/2 cols

    float* biasS = (float*)smem;
    const uint32_t st0 = smem_to_u32(smem) + 1024;

    if (tid < NT) biasS[tid] = sb[n0 + tid] + db[j * NOUT + n0 + tid];

    const bf16* Aj_hi = Ahi + (size_t)j * a_jstride + (size_t)m0 * lda;
    const bf16* Aj_lo = Alo + (size_t)j * a_jstride + (size_t)m0 * lda;
    const bf16* Wj_hi = Whi + ((size_t)j * NOUT + n0) * K;
    const bf16* Wj_lo = Wlo + ((size_t)j * NOUT + n0) * K;

    const int NC = K >> 6;

    // preload chunk 0 -> buf 0
    load_tile<128>(Aj_hi, lda, st0, tid);
    load_tile<128>(Aj_lo, lda, st0 + ABYTES, tid);
    load_tile<NT>(Wj_hi, K, st0 + 2 * ABYTES, tid);
    load_tile<NT>(Wj_lo, K, st0 + 2 * ABYTES + BBYTES, tid);
    CP_COMMIT();

    // accumulators: 2 m-subtiles x NSUB n-subtiles (per warp covers NT/2 cols -> NSUB/?):
    // warp layout 4x2: wm in {0,32,64,96}, wn in {0, NT/2}; per-warp n-subtiles = NT/16
    const int wm = (wid & 3) * 32;
    const int wn = (wid >> 2) * (NT / 2);
    float acc[2][NSUB][4];
#pragma unroll
    for (int i = 0; i < 2; i++)
#pragma unroll
        for (int s = 0; s < NSUB; s++)
#pragma unroll
            for (int q = 0; q < 4; q++) acc[i][s][q] = 0.f;

    for (int c = 0; c < NC; c++) {
        if (c + 1 < NC) {
            uint32_t nb = st0 + ((c + 1) & 1) * BUF;
            int ko = (c + 1) * 64;
            load_tile<128>(Aj_hi + ko, lda, nb, tid);
            load_tile<128>(Aj_lo + ko, lda, nb + ABYTES, tid);
            load_tile<NT>(Wj_hi + ko, K, nb + 2 * ABYTES, tid);
            load_tile<NT>(Wj_lo + ko, K, nb + 2 * ABYTES + BBYTES, tid);
            CP_COMMIT();
            CP_WAIT(1);
        } else {
            CP_WAIT(0);
        }
        __syncthreads();

        const uint32_t bu = st0 + (c & 1) * BUF;
        const uint32_t aHi = bu, aLo = bu + ABYTES;
        const uint32_t bHi = bu + 2 * ABYTES, bLo = bHi + BBYTES;

#pragma unroll
        for (int ks = 0; ks < 4; ks++) {
            const int kc = ks * 2;
            // A fragments (hi, lo) for 2 m-subtiles
            uint32_t ah[2][4], al[2][4];
#pragma unroll
            for (int i = 0; i < 2; i++) {
                int row = wm + i * 16 + (lane & 15);
                int cc = kc + (lane >> 4);
                int o = swz(row, cc);
                ldsm_x4(ah[i], aHi + o);
                ldsm_x4(al[i], aLo + o);
            }
            // B pairs: each x4 loads 2 n-subtiles (n, n+8)
#pragma unroll
            for (int p = 0; p < NSUB / 2; p++) {
                int row = wn + p * 16 + ((lane >> 4) & 1) * 8 + (lane & 7);
                int cc = kc + ((lane >> 3) & 1);
                int o = swz(row, cc);
                uint32_t bh[4], bl[4];
                ldsm_x4(bh, bHi + o);
                ldsm_x4(bl, bLo + o);
#pragma unroll
                for (int i = 0; i < 2; i++) {
                    mma16816(acc[i][2 * p + 0], ah[i], bh + 0);
                    mma16816(acc[i][2 * p + 1], ah[i], bh + 2);
                    mma16816(acc[i][2 * p + 0], ah[i], bl + 0);
                    mma16816(acc[i][2 * p + 1], ah[i], bl + 2);
                    mma16816(acc[i][2 * p + 0], al[i], bh + 0);
                    mma16816(acc[i][2 * p + 1], al[i], bh + 2);
                }
            }
        }
        __syncthreads();
    }

    // -------------------- epilogue --------------------
    // C frag: c0,c1 -> row t/4,   cols (t%4)*2 + {0,1}
    //         c2,c3 -> row t/4+8, same cols
#pragma unroll
    for (int i = 0; i < 2; i++) {
#pragma unroll
        for (int s = 0; s < NSUB; s++) {
            int ncol = wn + s * 8 + (lane & 3) * 2;
            float b0 = biasS[ncol], b1 = biasS[ncol + 1];
#pragma unroll
            for (int h = 0; h < 2; h++) {
                int row = m0 + wm + i * 16 + (lane >> 2) + h * 8;
                float v0 = fmaxf(acc[i][s][2 * h + 0] + b0, 0.f);
                float v1 = fmaxf(acc[i][s][2 * h + 1] + b1, 0.f);
                size_t o = ((size_t)j * B_ROWS + row) * NOUT + n0 + ncol;
                if (FP32OUT) {
                    *(float2*)(outF + o) = make_float2(v0, v1);
                } else {
                    bf16 h0 = __float2bfloat16(v0);
                    bf16 h1 = __float2bfloat16(v1);
                    bf16 l0 = __float2bfloat16(v0 - __bfloat162float(h0));
                    bf16 l1 = __float2bfloat16(v1 - __bfloat162float(h1));
                    *(uint32_t*)(outHi + o) =
                        (uint32_t)__bfloat16_as_ushort(h0) |
                        ((uint32_t)__bfloat16_as_ushort(h1) << 16);
                    *(uint32_t*)(outLo + o) =
                        (uint32_t)__bfloat16_as_ushort(l0) |
                        ((uint32_t)__bfloat16_as_ushort(l1) << 16);
                }
            }
        }
    }
}

// ---------------------------------------------------------------------------
// domain mix: out[b][:] = sum_j ind[b][j] * h2[j][b][:]
// ---------------------------------------------------------------------------
__global__ void mix_kernel(const float* __restrict__ h2, const float* __restrict__ ind,
                           float* __restrict__ out) {
    int idx = blockIdx.x * blockDim.x + threadIdx.x;
    int b = idx >> 4, q = idx & 15;
    const float4* h4 = (const float4*)h2;
    float4 acc = make_float4(0.f, 0.f, 0.f, 0.f);
#pragma unroll
    for (int j = 0; j < J_DOM; j++) {
        float s = __ldg(ind + (size_t)b * J_DOM + j);
        float4 h = __ldg(&h4[((size_t)j * B_ROWS + b) * 16 + q]);
        acc.x += s * h.x; acc.y += s * h.y; acc.z += s * h.z; acc.w += s * h.w;
    }
    ((float4*)out)[idx] = acc;
}

// ---------------------------------------------------------------------------
extern "C" void kernel_launch(void* const* d_in, const int* in_sizes, int n_in,
                              void* d_out, int out_size) {
    const float* x   = (const float*)d_in[0];
    const float* ind = (const float*)d_in[1];
    const float* sk0 = (const float*)d_in[2];
    const float* sb0 = (const float*)d_in[3];
    const float* dk0 = (const float*)d_in[4];
    const float* db0 = (const float*)d_in[5];
    const float* sk1 = (const float*)d_in[6];
    const float* sb1 = (const float*)d_in[7];
    const float* dk1 = (const float*)d_in[8];
    const float* db1 = (const float*)d_in[9];
    const float* sk2 = (const float*)d_in[10];
    const float* sb2 = (const float*)d_in[11];
    const float* dk2 = (const float*)d_in[12];
    const float* db2 = (const float*)d_in[13];
    float* out = (float*)d_out;

    bf16 *xhi, *xlo, *w0h, *w0l, *w1h, *w1l, *w2h, *w2l, *h0h, *h0l, *h1h, *h1l;
    float* h2;
    cudaGetSymbolAddress((void**)&xhi, g_xhi);
    cudaGetSymbolAddress((void**)&xlo, g_xlo);
    cudaGetSymbolAddress((void**)&w0h, g_w0hi);
    cudaGetSymbolAddress((void**)&w0l, g_w0lo);
    cudaGetSymbolAddress((void**)&w1h, g_w1hi);
    cudaGetSymbolAddress((void**)&w1l, g_w1lo);
    cudaGetSymbolAddress((void**)&w2h, g_w2hi);
    cudaGetSymbolAddress((void**)&w2l, g_w2lo);
    cudaGetSymbolAddress((void**)&h0h, g_h0hi);
    cudaGetSymbolAddress((void**)&h0l, g_h0lo);
    cudaGetSymbolAddress((void**)&h1h, g_h1hi);
    cudaGetSymbolAddress((void**)&h1l, g_h1lo);
    cudaGetSymbolAddress((void**)&h2, g_h2);

    {
        size_t tx = (size_t)B_ROWS * D0;
        conv_split<<<(unsigned)((tx + 255) / 256), 256>>>(x, xhi, xlo, tx);
        int t0 = J_DOM * D0 * H0, t1 = J_DOM * H0 * H1, t2 = J_DOM * H1 * H2;
        fuse_wT<<<(t0 + 255) / 256, 256>>>(sk0, dk0, w0h, w0l, D0, H0, t0);
        fuse_wT<<<(t1 + 255) / 256, 256>>>(sk1, dk1, w1h, w1l, H0, H1, t1);
        fuse_wT<<<(t2 + 255) / 256, 256>>>(sk2, dk2, w2h, w2l, H1, H2, t2);
    }

    constexpr int SM128 = 1024 + 2 * (2 * 128 * 128 + 2 * 128 * 128);  // 132096
    constexpr int SM64  = 1024 + 2 * (2 * 128 * 128 + 2 * 64 * 128);   //  99328
    cudaFuncSetAttribute(gemm_hmma<128, false>, cudaFuncAttributeMaxDynamicSharedMemorySize, SM128);
    cudaFuncSetAttribute(gemm_hmma<64,  true >, cudaFuncAttributeMaxDynamicSharedMemorySize, SM64);

    // layer 0: A = x (shared across j), K=512, N=256 (2 n-blocks of 128)
    gemm_hmma<128, false><<<dim3(J_DOM, B_ROWS / 128, 2), 256, SM128>>>(
        xhi, xlo, (size_t)0, D0, w0h, w0l, sb0, db0, h0h, h0l, nullptr, D0, H0);

    // layer 1: A = h0[j], K=256, N=128
    gemm_hmma<128, false><<<dim3(J_DOM, B_ROWS / 128, 1), 256, SM128>>>(
        h0h, h0l, (size_t)B_ROWS * H0, H0, w1h, w1l, sb1, db1, h1h, h1l, nullptr, H0, H1);

    // layer 2: A = h1[j], K=128, N=64, fp32 out
    gemm_hmma<64, true><<<dim3(J_DOM, B_ROWS / 128, 1), 256, SM64>>>(
        h1h, h1l, (size_t)B_ROWS * H1, H1, w2h, w2l, sb2, db2, nullptr, nullptr, h2, H1, H2);

    // domain mix
    mix_kernel<<<B_ROWS * 16 / 256, 256>>>(h2, ind, out);
}

// round 9
// speedup vs baseline: 2.5740x; 1.1620x over previous
#include <cuda_runtime.h>
#include <cuda_bf16.h>
#include <cstdint>

// Problem constants
#define B_ROWS 65536
#define J_DOM  8
#define D0 512
#define H0 256
#define H1 128
#define H2 64

typedef __nv_bfloat16 bf16;

// ---------------------------------------------------------------------------
// baseline-PTX helpers (HMMA mma.sync + ldmatrix + cp.async only)
// ---------------------------------------------------------------------------
__device__ __forceinline__ uint32_t smem_to_u32(const void* p) {
    uint32_t a;
    asm("{ .reg .u64 t; cvta.to.shared.u64 t, %1; cvt.u32.u64 %0, t; }" : "=r"(a) : "l"(p));
    return a;
}
__device__ __forceinline__ void ldsm_x4(uint32_t* r, uint32_t addr) {
    asm volatile("ldmatrix.sync.aligned.m8n8.x4.shared.b16 {%0,%1,%2,%3}, [%4];"
                 : "=r"(r[0]), "=r"(r[1]), "=r"(r[2]), "=r"(r[3]) : "r"(addr));
}
__device__ __forceinline__ void mma16816(float* c, const uint32_t* a, const uint32_t* b) {
    asm volatile(
        "mma.sync.aligned.m16n8k16.row.col.f32.bf16.bf16.f32 "
        "{%0,%1,%2,%3}, {%4,%5,%6,%7}, {%8,%9}, {%0,%1,%2,%3};"
        : "+f"(c[0]), "+f"(c[1]), "+f"(c[2]), "+f"(c[3])
        : "r"(a[0]), "r"(a[1]), "r"(a[2]), "r"(a[3]), "r"(b[0]), "r"(b[1]));
}
__device__ __forceinline__ void cp16(uint32_t sm, const void* g) {
    asm volatile("cp.async.cg.shared.global [%0], [%1], 16;" :: "r"(sm), "l"(g));
}
#define CP_COMMIT() asm volatile("cp.async.commit_group;" ::: "memory")
#define CP_WAIT(n)  asm volatile("cp.async.wait_group %0;" :: "n"(n) : "memory")
__device__ __forceinline__ void sts32(uint32_t addr, uint32_t v) {
    asm volatile("st.shared.b32 [%0], %1;" :: "r"(addr), "r"(v));
}

// swizzled byte offset within a [rows x 64 bf16] tile (128B rows, 16B chunks)
__device__ __forceinline__ int swz(int row, int c) {
    return row * 128 + ((c ^ (row & 7)) << 4);
}

// ---------------------------------------------------------------------------
// Device scratch
// ---------------------------------------------------------------------------
__device__ bf16 g_xhi[(size_t)B_ROWS * D0];
__device__ bf16 g_xlo[(size_t)B_ROWS * D0];
__device__ bf16 g_w0hi[J_DOM * D0 * H0];     // [J][N][K]
__device__ bf16 g_w0lo[J_DOM * D0 * H0];
__device__ bf16 g_w1hi[J_DOM * H0 * H1];
__device__ bf16 g_w1lo[J_DOM * H0 * H1];
__device__ bf16 g_w2hi[J_DOM * H1 * H2];
__device__ bf16 g_w2lo[J_DOM * H1 * H2];

// ---------------------------------------------------------------------------
// prologue kernels
// ---------------------------------------------------------------------------
__global__ void conv_split(const float* __restrict__ x, bf16* __restrict__ hi,
                           bf16* __restrict__ lo, size_t total) {
    size_t i = (size_t)blockIdx.x * blockDim.x + threadIdx.x;
    if (i < total) {
        float v = x[i];
        bf16 h = __float2bfloat16(v);
        hi[i] = h;
        lo[i] = __float2bfloat16(v - __bfloat162float(h));
    }
}
__global__ void fuse_wT(const float* __restrict__ sk, const float* __restrict__ dk,
                        bf16* __restrict__ whi, bf16* __restrict__ wlo,
                        int K, int N, int total) {
    int i = blockIdx.x * blockDim.x + threadIdx.x;
    if (i < total) {
        int r = i % (K * N);
        int j = i / (K * N);
        int k = r / N, n = r % N;
        float v = sk[r] * dk[i];
        bf16 h = __float2bfloat16(v);
        size_t o = (size_t)j * K * N + (size_t)n * K + k;
        whi[o] = h;
        wlo[o] = __float2bfloat16(v - __bfloat162float(h));
    }
}

// async tile loader: [ROWS x 64 bf16] K-major -> swizzled SMEM
template<int ROWS>
__device__ __forceinline__ void load_tile(const bf16* __restrict__ src, int pitch,
                                          uint32_t dst, int tid) {
#pragma unroll
    for (int it = 0; it < ROWS / 32; it++) {
        int idx = tid + it * 256;
        int row = idx >> 3, c = idx & 7;
        cp16(dst + swz(row, c), src + (size_t)row * pitch + c * 8);
    }
}

// ---------------------------------------------------------------------------
// one K=64 chunk of 3-pass split-bf16 MMAs.  A tile: 128 rows.  B tile: PAIRS*16 rows.
// pass-major ordering to break same-accumulator chains.
// ---------------------------------------------------------------------------
template<int PAIRS>
__device__ __forceinline__ void chunk_mma(
    float (&acc)[2][2 * PAIRS][4],
    uint32_t aHi, uint32_t aLo, uint32_t bHi, uint32_t bLo,
    int lane, int wm, int wn)
{
#pragma unroll
    for (int ks = 0; ks < 4; ks++) {
        const int kc = ks * 2;
        uint32_t ah[2][4], al[2][4];
#pragma unroll
        for (int i = 0; i < 2; i++) {
            int row = wm + i * 16 + (lane & 15);
            int o = swz(row, kc + (lane >> 4));
            ldsm_x4(ah[i], aHi + o);
            ldsm_x4(al[i], aLo + o);
        }
#pragma unroll
        for (int p = 0; p < PAIRS; p++) {
            int row = wn + p * 16 + ((lane >> 4) & 1) * 8 + (lane & 7);
            int o = swz(row, kc + ((lane >> 3) & 1));
            uint32_t bh[4], bl[4];
            ldsm_x4(bh, bHi + o);
            ldsm_x4(bl, bLo + o);
#pragma unroll
            for (int i = 0; i < 2; i++) {
                mma16816(acc[i][2 * p + 0], ah[i], bh + 0);
                mma16816(acc[i][2 * p + 1], ah[i], bh + 2);
            }
#pragma unroll
            for (int i = 0; i < 2; i++) {
                mma16816(acc[i][2 * p + 0], ah[i], bl + 0);
                mma16816(acc[i][2 * p + 1], ah[i], bl + 2);
            }
#pragma unroll
            for (int i = 0; i < 2; i++) {
                mma16816(acc[i][2 * p + 0], al[i], bh + 0);
                mma16816(acc[i][2 * p + 1], al[i], bh + 2);
            }
        }
    }
}

// epilogue: bias + relu + hi/lo split, C-frags -> swizzled SMEM A-layout
// dst layout: per k64-chunk c: [c*32768 .. ) hi tile 16KB, +16384 lo tile
template<int NSUB>
__device__ __forceinline__ void epi_split(
    float (&acc)[2][NSUB][4], const float* __restrict__ bias,
    uint32_t dstBase, int lane, int wm, int wn)
{
#pragma unroll
    for (int i = 0; i < 2; i++) {
#pragma unroll
        for (int s = 0; s < NSUB; s++) {
            int n = wn + s * 8 + (lane & 3) * 2;
            float b0 = bias[n], b1 = bias[n + 1];
            int cA = n >> 6, cc = n & 63;
#pragma unroll
            for (int h = 0; h < 2; h++) {
                int row = wm + i * 16 + (lane >> 2) + h * 8;
                float v0 = fmaxf(acc[i][s][2 * h + 0] + b0, 0.f);
                float v1 = fmaxf(acc[i][s][2 * h + 1] + b1, 0.f);
                bf16 h0 = __float2bfloat16(v0);
                bf16 h1 = __float2bfloat16(v1);
                bf16 l0 = __float2bfloat16(v0 - __bfloat162float(h0));
                bf16 l1 = __float2bfloat16(v1 - __bfloat162float(h1));
                uint32_t hw = (uint32_t)__bfloat16_as_ushort(h0) |
                              ((uint32_t)__bfloat16_as_ushort(h1) << 16);
                uint32_t lw = (uint32_t)__bfloat16_as_ushort(l0) |
                              ((uint32_t)__bfloat16_as_ushort(l1) << 16);
                uint32_t ad = dstBase + cA * 32768 + swz(row, cc >> 3) + (cc & 7) * 2;
                sts32(ad, hw);
                sts32(ad + 16384, lw);
            }
        }
    }
}

// ---------------------------------------------------------------------------
// fully fused STAR kernel: per CTA 128 batch rows, loop j, L0->L1->L2->mix
// SMEM map (byte offsets, total 198656):
//   [0,1024)        bias0 (256 f)
//   [1024,1536)     bias1 (128 f)
//   [1536,1792)     bias2 (64 f)
//   phase A: [2048, 198656)  two 98304B stages: {xh 16K | xl 16K | wh 32K | wl 32K}
//   phase B: h0 at [2048,133120)  4 chunks x {hi 16K, lo 16K};  W1 stages [133120,198656)
//   phase C: h1 at [133120,198656) 2 chunks x {hi 16K, lo 16K}; W2 at [2048,34816)
// ---------------------------------------------------------------------------
__global__ void __launch_bounds__(256, 1) star_fused(
    const bf16* __restrict__ xhi, const bf16* __restrict__ xlo,
    const bf16* __restrict__ w0h, const bf16* __restrict__ w0l,
    const bf16* __restrict__ w1h, const bf16* __restrict__ w1l,
    const bf16* __restrict__ w2h, const bf16* __restrict__ w2l,
    const float* __restrict__ sb0, const float* __restrict__ db0,
    const float* __restrict__ sb1, const float* __restrict__ db1,
    const float* __restrict__ sb2, const float* __restrict__ db2,
    const float* __restrict__ ind, float* __restrict__ out)
{
    extern __shared__ char smem[];
    const int tid = threadIdx.x, lane = tid & 31, wid = tid >> 5;
    const int m0 = blockIdx.x * 128;
    const int wm  = (wid & 3) * 32;
    const int wnA = (wid >> 2) * 128;
    const int wnB = (wid >> 2) * 64;
    const int wnC = (wid >> 2) * 32;

    float* bias0 = (float*)smem;
    float* bias1 = (float*)(smem + 1024);
    float* bias2 = (float*)(smem + 1536);
    const uint32_t sbase = smem_to_u32(smem);
    const uint32_t BUF = sbase + 2048;      // phase A stages (2 x 98304)
    const uint32_t H0S = sbase + 2048;      // h0: 4 chunks x 32768
    const uint32_t W1S = sbase + 133120;    // W1 stages (2 x 32768)
    const uint32_t H1S = sbase + 133120;    // h1: 2 chunks x 32768
    const uint32_t W2S = sbase + 2048;      // W2: 2 chunks x 16384

    float outacc[2][4][4];
#pragma unroll
    for (int i = 0; i < 2; i++)
#pragma unroll
        for (int s = 0; s < 4; s++)
#pragma unroll
            for (int q = 0; q < 4; q++) outacc[i][s][q] = 0.f;

    const bf16* Axh = xhi + (size_t)m0 * D0;
    const bf16* Axl = xlo + (size_t)m0 * D0;

    for (int j = 0; j < J_DOM; j++) {
        __syncthreads();   // protect bias + SMEM regions from previous j readers
        if (tid < 256) bias0[tid] = sb0[tid] + db0[j * H0 + tid];
        if (tid < 128) bias1[tid] = sb1[tid] + db1[j * H1 + tid];
        if (tid < 64)  bias2[tid] = sb2[tid] + db2[j * H2 + tid];

        // ================= phase A: L0  (K=512, N=256) =================
        const bf16* W0hp = w0h + (size_t)j * H0 * D0;
        const bf16* W0lp = w0l + (size_t)j * H0 * D0;

        load_tile<128>(Axh, D0, BUF + 0,     tid);
        load_tile<128>(Axl, D0, BUF + 16384, tid);
        load_tile<256>(W0hp, D0, BUF + 32768, tid);
        load_tile<256>(W0lp, D0, BUF + 65536, tid);
        CP_COMMIT();

        float acc0[2][16][4];
#pragma unroll
        for (int i = 0; i < 2; i++)
#pragma unroll
            for (int s = 0; s < 16; s++)
#pragma unroll
                for (int q = 0; q < 4; q++) acc0[i][s][q] = 0.f;

        for (int c = 0; c < 8; c++) {
            if (c + 1 < 8) {
                uint32_t nb = BUF + ((c + 1) & 1) * 98304;
                int ko = (c + 1) * 64;
                load_tile<128>(Axh + ko, D0, nb, tid);
                load_tile<128>(Axl + ko, D0, nb + 16384, tid);
                load_tile<256>(W0hp + ko, D0, nb + 32768, tid);
                load_tile<256>(W0lp + ko, D0, nb + 65536, tid);
                CP_COMMIT();
                CP_WAIT(1);
            } else {
                CP_WAIT(0);
            }
            __syncthreads();
            uint32_t bu = BUF + (c & 1) * 98304;
            chunk_mma<8>(acc0, bu, bu + 16384, bu + 32768, bu + 65536, lane, wm, wnA);
            __syncthreads();
        }

        // preload W1 now (W1S region's last reader was chunk-7 MMA, fenced above);
        // overlaps the cp.async with the h0 epilogue math.
        const bf16* W1hp = w1h + (size_t)j * H1 * H0;
        const bf16* W1lp = w1l + (size_t)j * H1 * H0;
        load_tile<128>(W1hp, H0, W1S + 0,     tid);
        load_tile<128>(W1lp, H0, W1S + 16384, tid);
        CP_COMMIT();

        // h0 -> SMEM (reuses phase-A buffer space)
        epi_split<16>(acc0, bias0, H0S, lane, wm, wnA);
        __syncthreads();

        // ================= phase B: L1  (K=256, N=128) =================
        float acc1[2][8][4];
#pragma unroll
        for (int i = 0; i < 2; i++)
#pragma unroll
            for (int s = 0; s < 8; s++)
#pragma unroll
                for (int q = 0; q < 4; q++) acc1[i][s][q] = 0.f;

        for (int c = 0; c < 4; c++) {
            if (c + 1 < 4) {
                uint32_t nb = W1S + ((c + 1) & 1) * 32768;
                int ko = (c + 1) * 64;
                load_tile<128>(W1hp + ko, H0, nb, tid);
                load_tile<128>(W1lp + ko, H0, nb + 16384, tid);
                CP_COMMIT();
                CP_WAIT(1);
            } else {
                CP_WAIT(0);
            }
            __syncthreads();
            uint32_t au = H0S + c * 32768;
            uint32_t bu = W1S + (c & 1) * 32768;
            chunk_mma<4>(acc1, au, au + 16384, bu, bu + 16384, lane, wm, wnB);
            __syncthreads();
        }

        // preload W2 now (W2S overlaps h0 chunk 0, last read at phase-B c=0, fenced);
        // overlaps the cp.async with the h1 epilogue math.
        const bf16* W2hp = w2h + (size_t)j * H2 * H1;
        const bf16* W2lp = w2l + (size_t)j * H2 * H1;
#pragma unroll
        for (int c = 0; c < 2; c++) {
            load_tile<64>(W2hp + c * 64, H1, W2S + c * 16384, tid);
            load_tile<64>(W2lp + c * 64, H1, W2S + c * 16384 + 8192, tid);
        }
        CP_COMMIT();

        // h1 -> SMEM (reuses W1 stage space; W1 stages dead after final sync)
        epi_split<8>(acc1, bias1, H1S, lane, wm, wnB);
        CP_WAIT(0);
        __syncthreads();

        // ================= phase C: L2 (K=128, N=64) + mix =================
        float acc2[2][4][4];
#pragma unroll
        for (int i = 0; i < 2; i++)
#pragma unroll
            for (int s = 0; s < 4; s++)
#pragma unroll
                for (int q = 0; q < 4; q++) acc2[i][s][q] = 0.f;

#pragma unroll
        for (int c = 0; c < 2; c++) {
            uint32_t au = H1S + c * 32768;
            uint32_t bu = W2S + c * 16384;
            chunk_mma<2>(acc2, au, au + 16384, bu, bu + 8192, lane, wm, wnC);
        }

        // mix-accumulate into persistent registers
#pragma unroll
        for (int i = 0; i < 2; i++) {
#pragma unroll
            for (int h = 0; h < 2; h++) {
                int row = wm + i * 16 + (lane >> 2) + h * 8;
                float iv = __ldg(ind + (size_t)(m0 + row) * J_DOM + j);
#pragma unroll
                for (int s = 0; s < 4; s++) {
                    int n = wnC + s * 8 + (lane & 3) * 2;
                    float v0 = fmaxf(acc2[i][s][2 * h + 0] + bias2[n], 0.f);
                    float v1 = fmaxf(acc2[i][s][2 * h + 1] + bias2[n + 1], 0.f);
                    outacc[i][s][2 * h + 0] = fmaf(iv, v0, outacc[i][s][2 * h + 0]);
                    outacc[i][s][2 * h + 1] = fmaf(iv, v1, outacc[i][s][2 * h + 1]);
                }
            }
        }
        // top-of-loop __syncthreads protects region reuse for next j
    }

    // final output write
#pragma unroll
    for (int i = 0; i < 2; i++) {
#pragma unroll
        for (int s = 0; s < 4; s++) {
            int n = wnC + s * 8 + (lane & 3) * 2;
#pragma unroll
            for (int h = 0; h < 2; h++) {
                int row = wm + i * 16 + (lane >> 2) + h * 8;
                *(float2*)(out + (size_t)(m0 + row) * H2 + n) =
                    make_float2(outacc[i][s][2 * h + 0], outacc[i][s][2 * h + 1]);
            }
        }
    }
}

// ---------------------------------------------------------------------------
extern "C" void kernel_launch(void* const* d_in, const int* in_sizes, int n_in,
                              void* d_out, int out_size) {
    const float* x   = (const float*)d_in[0];
    const float* ind = (const float*)d_in[1];
    const float* sk0 = (const float*)d_in[2];
    const float* sb0 = (const float*)d_in[3];
    const float* dk0 = (const float*)d_in[4];
    const float* db0 = (const float*)d_in[5];
    const float* sk1 = (const float*)d_in[6];
    const float* sb1 = (const float*)d_in[7];
    const float* dk1 = (const float*)d_in[8];
    const float* db1 = (const float*)d_in[9];
    const float* sk2 = (const float*)d_in[10];
    const float* sb2 = (const float*)d_in[11];
    const float* dk2 = (const float*)d_in[12];
    const float* db2 = (const float*)d_in[13];
    float* out = (float*)d_out;

    bf16 *xhi, *xlo, *w0h, *w0l, *w1h, *w1l, *w2h, *w2l;
    cudaGetSymbolAddress((void**)&xhi, g_xhi);
    cudaGetSymbolAddress((void**)&xlo, g_xlo);
    cudaGetSymbolAddress((void**)&w0h, g_w0hi);
    cudaGetSymbolAddress((void**)&w0l, g_w0lo);
    cudaGetSymbolAddress((void**)&w1h, g_w1hi);
    cudaGetSymbolAddress((void**)&w1l, g_w1lo);
    cudaGetSymbolAddress((void**)&w2h, g_w2hi);
    cudaGetSymbolAddress((void**)&w2l, g_w2lo);

    {
        size_t tx = (size_t)B_ROWS * D0;
        conv_split<<<(unsigned)((tx + 255) / 256), 256>>>(x, xhi, xlo, tx);
        int t0 = J_DOM * D0 * H0, t1 = J_DOM * H0 * H1, t2 = J_DOM * H1 * H2;
        fuse_wT<<<(t0 + 255) / 256, 256>>>(sk0, dk0, w0h, w0l, D0, H0, t0);
        fuse_wT<<<(t1 + 255) / 256, 256>>>(sk1, dk1, w1h, w1l, H0, H1, t1);
        fuse_wT<<<(t2 + 255) / 256, 256>>>(sk2, dk2, w2h, w2l, H1, H2, t2);
    }

    constexpr int SMEM = 198656;
    cudaFuncSetAttribute(star_fused, cudaFuncAttributeMaxDynamicSharedMemorySize, SMEM);

    star_fused<<<B_ROWS / 128, 256, SMEM>>>(
        xhi, xlo, w0h, w0l, w1h, w1l, w2h, w2l,
        sb0, db0, sb1, db1, sb2, db2, ind, out);
}

// round 11
// speedup vs baseline: 3.5899x; 1.3947x over previous
#include <cuda_runtime.h>
#include <cuda_fp16.h>
#include <cstdint>

// Problem constants
#define B_ROWS 65536
#define J_DOM  8
#define D0 512
#define H0 256
#define H1 128
#define H2 64

// ---------------------------------------------------------------------------
// baseline-PTX helpers (HMMA mma.sync + ldmatrix + cp.async only)
// ---------------------------------------------------------------------------
__device__ __forceinline__ uint32_t smem_to_u32(const void* p) {
    uint32_t a;
    asm("{ .reg .u64 t; cvta.to.shared.u64 t, %1; cvt.u32.u64 %0, t; }" : "=r"(a) : "l"(p));
    return a;
}
__device__ __forceinline__ void ldsm_x4(uint32_t* r, uint32_t addr) {
    asm volatile("ldmatrix.sync.aligned.m8n8.x4.shared.b16 {%0,%1,%2,%3}, [%4];"
                 : "=r"(r[0]), "=r"(r[1]), "=r"(r[2]), "=r"(r[3]) : "r"(addr));
}
__device__ __forceinline__ void mma16816(float* c, const uint32_t* a, const uint32_t* b) {
    asm volatile(
        "mma.sync.aligned.m16n8k16.row.col.f32.f16.f16.f32 "
        "{%0,%1,%2,%3}, {%4,%5,%6,%7}, {%8,%9}, {%0,%1,%2,%3};"
        : "+f"(c[0]), "+f"(c[1]), "+f"(c[2]), "+f"(c[3])
        : "r"(a[0]), "r"(a[1]), "r"(a[2]), "r"(a[3]), "r"(b[0]), "r"(b[1]));
}
__device__ __forceinline__ void cp16(uint32_t sm, const void* g) {
    asm volatile("cp.async.cg.shared.global [%0], [%1], 16;" :: "r"(sm), "l"(g));
}
#define CP_COMMIT() asm volatile("cp.async.commit_group;" ::: "memory")
#define CP_WAIT(n)  asm volatile("cp.async.wait_group %0;" :: "n"(n) : "memory")
__device__ __forceinline__ void sts32(uint32_t addr, uint32_t v) {
    asm volatile("st.shared.b32 [%0], %1;" :: "r"(addr), "r"(v));
}

// swizzled byte offset within a [rows x 64 halfs] tile (128B rows, 16B chunks)
__device__ __forceinline__ int swz(int row, int c) {
    return row * 128 + ((c ^ (row & 7)) << 4);
}

// ---------------------------------------------------------------------------
// Device scratch
// ---------------------------------------------------------------------------
__device__ __half g_xh[(size_t)B_ROWS * D0];      // 64 MB, fp16 x
__device__ __half g_w0hi[J_DOM * D0 * H0];        // [J][N][K]
__device__ __half g_w0lo[J_DOM * D0 * H0];
__device__ __half g_w1hi[J_DOM * H0 * H1];
__device__ __half g_w1lo[J_DOM * H0 * H1];
__device__ __half g_w2hi[J_DOM * H1 * H2];
__device__ __half g_w2lo[J_DOM * H1 * H2];

// ---------------------------------------------------------------------------
// prologue kernels
// ---------------------------------------------------------------------------
__global__ void conv_half(const float* __restrict__ x, __half* __restrict__ o, size_t total) {
    size_t i = (size_t)blockIdx.x * blockDim.x + threadIdx.x;
    if (i < total) o[i] = __float2half(x[i]);
}
// fuse w[j,k,n]=sk[k,n]*dk[j,k,n]; store transposed [j][n][k], fp16 hi/lo split
__global__ void fuse_wT(const float* __restrict__ sk, const float* __restrict__ dk,
                        __half* __restrict__ whi, __half* __restrict__ wlo,
                        int K, int N, int total) {
    int i = blockIdx.x * blockDim.x + threadIdx.x;
    if (i < total) {
        int r = i % (K * N);
        int j = i / (K * N);
        int k = r / N, n = r % N;
        float v = sk[r] * dk[i];
        __half h = __float2half(v);
        size_t o = (size_t)j * K * N + (size_t)n * K + k;
        whi[o] = h;
        wlo[o] = __float2half(v - __half2float(h));
    }
}

// async tile loader: [ROWS x 64 halfs] K-major -> swizzled SMEM
template<int ROWS>
__device__ __forceinline__ void load_tile(const __half* __restrict__ src, int pitch,
                                          uint32_t dst, int tid) {
#pragma unroll
    for (int it = 0; it < ROWS / 32; it++) {
        int idx = tid + it * 256;
        int row = idx >> 3, c = idx & 7;
        cp16(dst + swz(row, c), src + (size_t)row * pitch + c * 8);
    }
}

// ---------------------------------------------------------------------------
// one K=64 chunk of 2-pass fp16 MMAs:  acc += A @ (Bhi + Blo)
// A tile: 128 rows (plain fp16).  B tile: PAIRS*16 rows per warp-half, hi+lo.
// ---------------------------------------------------------------------------
template<int PAIRS>
__device__ __forceinline__ void chunk_mma(
    float (&acc)[2][2 * PAIRS][4],
    uint32_t aT, uint32_t bHi, uint32_t bLo,
    int lane, int wm, int wn)
{
#pragma unroll
    for (int ks = 0; ks < 4; ks++) {
        const int kc = ks * 2;
        uint32_t ah[2][4];
#pragma unroll
        for (int i = 0; i < 2; i++) {
            int row = wm + i * 16 + (lane & 15);
            int o = swz(row, kc + (lane >> 4));
            ldsm_x4(ah[i], aT + o);
        }
#pragma unroll
        for (int p = 0; p < PAIRS; p++) {
            int row = wn + p * 16 + ((lane >> 4) & 1) * 8 + (lane & 7);
            int o = swz(row, kc + ((lane >> 3) & 1));
            uint32_t bh[4], bl[4];
            ldsm_x4(bh, bHi + o);
            ldsm_x4(bl, bLo + o);
#pragma unroll
            for (int i = 0; i < 2; i++) {
                mma16816(acc[i][2 * p + 0], ah[i], bh + 0);
                mma16816(acc[i][2 * p + 1], ah[i], bh + 2);
            }
#pragma unroll
            for (int i = 0; i < 2; i++) {
                mma16816(acc[i][2 * p + 0], ah[i], bl + 0);
                mma16816(acc[i][2 * p + 1], ah[i], bl + 2);
            }
        }
    }
}

// epilogue: bias + relu + fp16 round, C-frags -> swizzled SMEM A-layout
// dst layout: per k64-chunk c (16KB each): dstBase + c*16384
template<int NSUB>
__device__ __forceinline__ void epi_half(
    float (&acc)[2][NSUB][4], const float* __restrict__ bias,
    uint32_t dstBase, int lane, int wm, int wn)
{
#pragma unroll
    for (int i = 0; i < 2; i++) {
#pragma unroll
        for (int s = 0; s < NSUB; s++) {
            int n = wn + s * 8 + (lane & 3) * 2;
            float b0 = bias[n], b1 = bias[n + 1];
            int cA = n >> 6, cc = n & 63;
#pragma unroll
            for (int h = 0; h < 2; h++) {
                int row = wm + i * 16 + (lane >> 2) + h * 8;
                float v0 = fmaxf(acc[i][s][2 * h + 0] + b0, 0.f);
                float v1 = fmaxf(acc[i][s][2 * h + 1] + b1, 0.f);
                uint32_t hw = (uint32_t)__half_as_ushort(__float2half(v0)) |
                              ((uint32_t)__half_as_ushort(__float2half(v1)) << 16);
                uint32_t ad = dstBase + cA * 16384 + swz(row, cc >> 3) + (cc & 7) * 2;
                sts32(ad, hw);
            }
        }
    }
}

// ---------------------------------------------------------------------------
// fully fused STAR kernel: per CTA 128 batch rows, loop j, L0->L1->L2->mix
// SMEM map (byte offsets, total 198656):
//   [0,2048)          bias0/1/2
//   phase A stages: BUF = [2048, 165888)  2 x 81920 {xh 16K | w0h 32K | w0l 32K}
//   H0S = [2048,  67584)   h0: 4 chunks x 16K      (overlaps BUF; fenced)
//   W1S = [67584, 133120)  W1: 2 stages x 32K {hi 16K, lo 16K}
//   H1S = [133120,165888)  h1: 2 chunks x 16K
//   W2S = [165888,198656)  W2: 2 chunks x 16K {hi 8K, lo 8K}
// ---------------------------------------------------------------------------
__global__ void __launch_bounds__(256, 1) star_fused(
    const __half* __restrict__ xh,
    const __half* __restrict__ w0h, const __half* __restrict__ w0l,
    const __half* __restrict__ w1h, const __half* __restrict__ w1l,
    const __half* __restrict__ w2h, const __half* __restrict__ w2l,
    const float* __restrict__ sb0, const float* __restrict__ db0,
    const float* __restrict__ sb1, const float* __restrict__ db1,
    const float* __restrict__ sb2, const float* __restrict__ db2,
    const float* __restrict__ ind, float* __restrict__ out)
{
    extern __shared__ char smem[];
    const int tid = threadIdx.x, lane = tid & 31, wid = tid >> 5;
    const int m0 = blockIdx.x * 128;
    const int wm  = (wid & 3) * 32;
    const int wnA = (wid >> 2) * 128;
    const int wnB = (wid >> 2) * 64;
    const int wnC = (wid >> 2) * 32;

    float* bias0 = (float*)smem;
    float* bias1 = (float*)(smem + 1024);
    float* bias2 = (float*)(smem + 1536);
    const uint32_t sbase = smem_to_u32(smem);
    const uint32_t BUF = sbase + 2048;      // 2 stages x 81920
    const uint32_t H0S = sbase + 2048;
    const uint32_t W1S = sbase + 67584;
    const uint32_t H1S = sbase + 133120;
    const uint32_t W2S = sbase + 165888;

    float outacc[2][4][4];
#pragma unroll
    for (int i = 0; i < 2; i++)
#pragma unroll
        for (int s = 0; s < 4; s++)
#pragma unroll
            for (int q = 0; q < 4; q++) outacc[i][s][q] = 0.f;

    const __half* Ax = xh + (size_t)m0 * D0;

    for (int j = 0; j < J_DOM; j++) {
        __syncthreads();   // protect bias + SMEM regions from previous j readers
        if (tid < 256) bias0[tid] = sb0[tid] + db0[j * H0 + tid];
        if (tid < 128) bias1[tid] = sb1[tid] + db1[j * H1 + tid];
        if (tid < 64)  bias2[tid] = sb2[tid] + db2[j * H2 + tid];

        // ================= phase A: L0  (K=512, N=256) =================
        const __half* W0hp = w0h + (size_t)j * H0 * D0;
        const __half* W0lp = w0l + (size_t)j * H0 * D0;

        load_tile<128>(Ax, D0, BUF + 0, tid);
        load_tile<256>(W0hp, D0, BUF + 16384, tid);
        load_tile<256>(W0lp, D0, BUF + 49152, tid);
        CP_COMMIT();

        float acc0[2][16][4];
#pragma unroll
        for (int i = 0; i < 2; i++)
#pragma unroll
            for (int s = 0; s < 16; s++)
#pragma unroll
                for (int q = 0; q < 4; q++) acc0[i][s][q] = 0.f;

        for (int c = 0; c < 8; c++) {
            if (c + 1 < 8) {
                uint32_t nb = BUF + ((c + 1) & 1) * 81920;
                int ko = (c + 1) * 64;
                load_tile<128>(Ax + ko, D0, nb, tid);
                load_tile<256>(W0hp + ko, D0, nb + 16384, tid);
                load_tile<256>(W0lp + ko, D0, nb + 49152, tid);
                CP_COMMIT();
                CP_WAIT(1);
            } else {
                CP_WAIT(0);
            }
            __syncthreads();
            uint32_t bu = BUF + (c & 1) * 81920;
            chunk_mma<8>(acc0, bu, bu + 16384, bu + 49152, lane, wm, wnA);
            __syncthreads();
        }

        // preload W1 (W1S region dead after chunk-7 sync); overlaps h0 epilogue
        const __half* W1hp = w1h + (size_t)j * H1 * H0;
        const __half* W1lp = w1l + (size_t)j * H1 * H0;
        load_tile<128>(W1hp, H0, W1S + 0,     tid);
        load_tile<128>(W1lp, H0, W1S + 16384, tid);
        CP_COMMIT();

        // h0 -> SMEM (fp16, 4 chunks x 16KB)
        epi_half<16>(acc0, bias0, H0S, lane, wm, wnA);
        __syncthreads();

        // ================= phase B: L1  (K=256, N=128) =================
        float acc1[2][8][4];
#pragma unroll
        for (int i = 0; i < 2; i++)
#pragma unroll
            for (int s = 0; s < 8; s++)
#pragma unroll
                for (int q = 0; q < 4; q++) acc1[i][s][q] = 0.f;

        for (int c = 0; c < 4; c++) {
            if (c + 1 < 4) {
                uint32_t nb = W1S + ((c + 1) & 1) * 32768;
                int ko = (c + 1) * 64;
                load_tile<128>(W1hp + ko, H0, nb, tid);
                load_tile<128>(W1lp + ko, H0, nb + 16384, tid);
                CP_COMMIT();
                CP_WAIT(1);
            } else {
                CP_WAIT(0);
            }
            __syncthreads();
            uint32_t au = H0S + c * 16384;
            uint32_t bu = W1S + (c & 1) * 32768;
            chunk_mma<4>(acc1, au, bu, bu + 16384, lane, wm, wnB);
            __syncthreads();
        }

        // preload W2 (W2S region dead since prior j phase C); overlaps h1 epilogue
        const __half* W2hp = w2h + (size_t)j * H2 * H1;
        const __half* W2lp = w2l + (size_t)j * H2 * H1;
#pragma unroll
        for (int c = 0; c < 2; c++) {
            load_tile<64>(W2hp + c * 64, H1, W2S + c * 16384, tid);
            load_tile<64>(W2lp + c * 64, H1, W2S + c * 16384 + 8192, tid);
        }
        CP_COMMIT();

        // h1 -> SMEM (fp16, 2 chunks x 16KB)
        epi_half<8>(acc1, bias1, H1S, lane, wm, wnB);
        CP_WAIT(0);
        __syncthreads();

        // ================= phase C: L2 (K=128, N=64) + mix =================
        float acc2[2][4][4];
#pragma unroll
        for (int i = 0; i < 2; i++)
#pragma unroll
            for (int s = 0; s < 4; s++)
#pragma unroll
                for (int q = 0; q < 4; q++) acc2[i][s][q] = 0.f;

#pragma unroll
        for (int c = 0; c < 2; c++) {
            uint32_t au = H1S + c * 16384;
            uint32_t bu = W2S + c * 16384;
            chunk_mma<2>(acc2, au, bu, bu + 8192, lane, wm, wnC);
        }

        // mix-accumulate into persistent registers
#pragma unroll
        for (int i = 0; i < 2; i++) {
#pragma unroll
            for (int h = 0; h < 2; h++) {
                int row = wm + i * 16 + (lane >> 2) + h * 8;
                float iv = __ldg(ind + (size_t)(m0 + row) * J_DOM + j);
#pragma unroll
                for (int s = 0; s < 4; s++) {
                    int n = wnC + s * 8 + (lane & 3) * 2;
                    float v0 = fmaxf(acc2[i][s][2 * h + 0] + bias2[n], 0.f);
                    float v1 = fmaxf(acc2[i][s][2 * h + 1] + bias2[n + 1], 0.f);
                    outacc[i][s][2 * h + 0] = fmaf(iv, v0, outacc[i][s][2 * h + 0]);
                    outacc[i][s][2 * h + 1] = fmaf(iv, v1, outacc[i][s][2 * h + 1]);
                }
            }
        }
        // top-of-loop __syncthreads protects region reuse for next j
    }

    // final output write
#pragma unroll
    for (int i = 0; i < 2; i++) {
#pragma unroll
        for (int s = 0; s < 4; s++) {
            int n = wnC + s * 8 + (lane & 3) * 2;
#pragma unroll
            for (int h = 0; h < 2; h++) {
                int row = wm + i * 16 + (lane >> 2) + h * 8;
                *(float2*)(out + (size_t)(m0 + row) * H2 + n) =
                    make_float2(outacc[i][s][2 * h + 0], outacc[i][s][2 * h + 1]);
            }
        }
    }
}

// ---------------------------------------------------------------------------
extern "C" void kernel_launch(void* const* d_in, const int* in_sizes, int n_in,
                              void* d_out, int out_size) {
    const float* x   = (const float*)d_in[0];
    const float* ind = (const float*)d_in[1];
    const float* sk0 = (const float*)d_in[2];
    const float* sb0 = (const float*)d_in[3];
    const float* dk0 = (const float*)d_in[4];
    const float* db0 = (const float*)d_in[5];
    const float* sk1 = (const float*)d_in[6];
    const float* sb1 = (const float*)d_in[7];
    const float* dk1 = (const float*)d_in[8];
    const float* db1 = (const float*)d_in[9];
    const float* sk2 = (const float*)d_in[10];
    const float* sb2 = (const float*)d_in[11];
    const float* dk2 = (const float*)d_in[12];
    const float* db2 = (const float*)d_in[13];
    float* out = (float*)d_out;

    __half *xh, *w0h, *w0l, *w1h, *w1l, *w2h, *w2l;
    cudaGetSymbolAddress((void**)&xh, g_xh);
    cudaGetSymbolAddress((void**)&w0h, g_w0hi);
    cudaGetSymbolAddress((void**)&w0l, g_w0lo);
    cudaGetSymbolAddress((void**)&w1h, g_w1hi);
    cudaGetSymbolAddress((void**)&w1l, g_w1lo);
    cudaGetSymbolAddress((void**)&w2h, g_w2hi);
    cudaGetSymbolAddress((void**)&w2l, g_w2lo);

    {
        size_t tx = (size_t)B_ROWS * D0;
        conv_half<<<(unsigned)((tx + 255) / 256), 256>>>(x, xh, tx);
        int t0 = J_DOM * D0 * H0, t1 = J_DOM * H0 * H1, t2 = J_DOM * H1 * H2;
        fuse_wT<<<(t0 + 255) / 256, 256>>>(sk0, dk0, w0h, w0l, D0, H0, t0);
        fuse_wT<<<(t1 + 255) / 256, 256>>>(sk1, dk1, w1h, w1l, H0, H1, t1);
        fuse_wT<<<(t2 + 255) / 256, 256>>>(sk2, dk2, w2h, w2l, H1, H2, t2);
    }

    constexpr int SMEM = 198656;
    cudaFuncSetAttribute(star_fused, cudaFuncAttributeMaxDynamicSharedMemorySize, SMEM);

    star_fused<<<B_ROWS / 128, 256, SMEM>>>(
        xh, w0h, w0l, w1h, w1l, w2h, w2l,
        sb0, db0, sb1, db1, sb2, db2, ind, out);
}

// round 12
// speedup vs baseline: 3.6288x; 1.0108x over previous
#include <cuda_runtime.h>
#include <cuda_fp16.h>
#include <cstdint>

// Problem constants
#define B_ROWS 65536
#define J_DOM  8
#define D0 512
#define H0 256
#define H1 128
#define H2 64

// ---------------------------------------------------------------------------
// baseline-PTX helpers (HMMA mma.sync + ldmatrix + cp.async only)
// ---------------------------------------------------------------------------
__device__ __forceinline__ uint32_t smem_to_u32(const void* p) {
    uint32_t a;
    asm("{ .reg .u64 t; cvta.to.shared.u64 t, %1; cvt.u32.u64 %0, t; }" : "=r"(a) : "l"(p));
    return a;
}
__device__ __forceinline__ void ldsm_x4(uint32_t* r, uint32_t addr) {
    asm volatile("ldmatrix.sync.aligned.m8n8.x4.shared.b16 {%0,%1,%2,%3}, [%4];"
                 : "=r"(r[0]), "=r"(r[1]), "=r"(r[2]), "=r"(r[3]) : "r"(addr));
}
__device__ __forceinline__ void mma16816(float* c, const uint32_t* a, const uint32_t* b) {
    asm volatile(
        "mma.sync.aligned.m16n8k16.row.col.f32.f16.f16.f32 "
        "{%0,%1,%2,%3}, {%4,%5,%6,%7}, {%8,%9}, {%0,%1,%2,%3};"
        : "+f"(c[0]), "+f"(c[1]), "+f"(c[2]), "+f"(c[3])
        : "r"(a[0]), "r"(a[1]), "r"(a[2]), "r"(a[3]), "r"(b[0]), "r"(b[1]));
}
__device__ __forceinline__ void cp16(uint32_t sm, const void* g) {
    asm volatile("cp.async.cg.shared.global [%0], [%1], 16;" :: "r"(sm), "l"(g));
}
#define CP_COMMIT() asm volatile("cp.async.commit_group;" ::: "memory")
#define CP_WAIT(n)  asm volatile("cp.async.wait_group %0;" :: "n"(n) : "memory")
__device__ __forceinline__ void sts32(uint32_t addr, uint32_t v) {
    asm volatile("st.shared.b32 [%0], %1;" :: "r"(addr), "r"(v));
}

// swizzled byte offset within a [rows x 64 halfs] tile (128B rows, 16B chunks)
__device__ __forceinline__ int swz(int row, int c) {
    return row * 128 + ((c ^ (row & 7)) << 4);
}

// ---------------------------------------------------------------------------
// Device scratch
// ---------------------------------------------------------------------------
__device__ __half g_xh[(size_t)B_ROWS * D0];      // 64 MB, fp16 x
__device__ __half g_w0[J_DOM * D0 * H0];          // [J][N][K] fp16
__device__ __half g_w1[J_DOM * H0 * H1];
__device__ __half g_w2[J_DOM * H1 * H2];

// ---------------------------------------------------------------------------
// prologue kernels
// ---------------------------------------------------------------------------
__global__ void conv_half(const float* __restrict__ x, __half* __restrict__ o, size_t total) {
    size_t i = (size_t)blockIdx.x * blockDim.x + threadIdx.x;
    if (i < total) o[i] = __float2half(x[i]);
}
// fuse w[j,k,n]=sk[k,n]*dk[j,k,n]; store transposed [j][n][k], fp16
__global__ void fuse_wT(const float* __restrict__ sk, const float* __restrict__ dk,
                        __half* __restrict__ w, int K, int N, int total) {
    int i = blockIdx.x * blockDim.x + threadIdx.x;
    if (i < total) {
        int r = i % (K * N);
        int j = i / (K * N);
        int k = r / N, n = r % N;
        w[(size_t)j * K * N + (size_t)n * K + k] = __float2half(sk[r] * dk[i]);
    }
}

// async tile loader: [ROWS x 64 halfs] K-major -> swizzled SMEM
template<int ROWS>
__device__ __forceinline__ void load_tile(const __half* __restrict__ src, int pitch,
                                          uint32_t dst, int tid) {
#pragma unroll
    for (int it = 0; it < ROWS / 32; it++) {
        int idx = tid + it * 256;
        int row = idx >> 3, c = idx & 7;
        cp16(dst + swz(row, c), src + (size_t)row * pitch + c * 8);
    }
}

// ---------------------------------------------------------------------------
// one K=64 chunk of single-pass fp16 MMAs:  acc += A @ B
// A tile: 128 rows.  B tile: PAIRS*16 rows per warp-half.
// ---------------------------------------------------------------------------
template<int PAIRS>
__device__ __forceinline__ void chunk_mma(
    float (&acc)[2][2 * PAIRS][4],
    uint32_t aT, uint32_t bW,
    int lane, int wm, int wn)
{
#pragma unroll
    for (int ks = 0; ks < 4; ks++) {
        const int kc = ks * 2;
        uint32_t ah[2][4];
#pragma unroll
        for (int i = 0; i < 2; i++) {
            int row = wm + i * 16 + (lane & 15);
            int o = swz(row, kc + (lane >> 4));
            ldsm_x4(ah[i], aT + o);
        }
#pragma unroll
        for (int p = 0; p < PAIRS; p++) {
            int row = wn + p * 16 + ((lane >> 4) & 1) * 8 + (lane & 7);
            int o = swz(row, kc + ((lane >> 3) & 1));
            uint32_t bh[4];
            ldsm_x4(bh, bW + o);
#pragma unroll
            for (int i = 0; i < 2; i++) {
                mma16816(acc[i][2 * p + 0], ah[i], bh + 0);
                mma16816(acc[i][2 * p + 1], ah[i], bh + 2);
            }
        }
    }
}

// epilogue: bias + relu + fp16 round, C-frags -> swizzled SMEM A-layout
// dst layout: per k64-chunk c (16KB each): dstBase + c*16384
template<int NSUB>
__device__ __forceinline__ void epi_half(
    float (&acc)[2][NSUB][4], const float* __restrict__ bias,
    uint32_t dstBase, int lane, int wm, int wn)
{
#pragma unroll
    for (int i = 0; i < 2; i++) {
#pragma unroll
        for (int s = 0; s < NSUB; s++) {
            int n = wn + s * 8 + (lane & 3) * 2;
            float b0 = bias[n], b1 = bias[n + 1];
            int cA = n >> 6, cc = n & 63;
#pragma unroll
            for (int h = 0; h < 2; h++) {
                int row = wm + i * 16 + (lane >> 2) + h * 8;
                float v0 = fmaxf(acc[i][s][2 * h + 0] + b0, 0.f);
                float v1 = fmaxf(acc[i][s][2 * h + 1] + b1, 0.f);
                uint32_t hw = (uint32_t)__half_as_ushort(__float2half(v0)) |
                              ((uint32_t)__half_as_ushort(__float2half(v1)) << 16);
                uint32_t ad = dstBase + cA * 16384 + swz(row, cc >> 3) + (cc & 7) * 2;
                sts32(ad, hw);
            }
        }
    }
}

// ---------------------------------------------------------------------------
// fully fused STAR kernel: per CTA 128 batch rows, loop j, L0->L1->L2->mix
// SMEM map (byte offsets, total 182272):
//   [0,2048)          bias0/1/2
//   BUF = [2048, 100352)   phase-A stages: 2 x 49152 {xh 16K | w0 32K}
//   H0S = [2048,  67584)   h0: 4 chunks x 16K      (overlaps BUF; fenced)
//   W1S = [100352,133120)  W1: 2 stages x 16K
//   H1S = [133120,165888)  h1: 2 chunks x 16K
//   W2S = [165888,182272)  W2: 2 chunks x 8K
// ---------------------------------------------------------------------------
__global__ void __launch_bounds__(256, 1) star_fused(
    const __half* __restrict__ xh,
    const __half* __restrict__ w0, const __half* __restrict__ w1,
    const __half* __restrict__ w2,
    const float* __restrict__ sb0, const float* __restrict__ db0,
    const float* __restrict__ sb1, const float* __restrict__ db1,
    const float* __restrict__ sb2, const float* __restrict__ db2,
    const float* __restrict__ ind, float* __restrict__ out)
{
    extern __shared__ char smem[];
    const int tid = threadIdx.x, lane = tid & 31, wid = tid >> 5;
    const int m0 = blockIdx.x * 128;
    const int wm  = (wid & 3) * 32;
    const int wnA = (wid >> 2) * 128;
    const int wnB = (wid >> 2) * 64;
    const int wnC = (wid >> 2) * 32;

    float* bias0 = (float*)smem;
    float* bias1 = (float*)(smem + 1024);
    float* bias2 = (float*)(smem + 1536);
    const uint32_t sbase = smem_to_u32(smem);
    const uint32_t BUF = sbase + 2048;      // 2 stages x 49152
    const uint32_t H0S = sbase + 2048;
    const uint32_t W1S = sbase + 100352;
    const uint32_t H1S = sbase + 133120;
    const uint32_t W2S = sbase + 165888;

    float outacc[2][4][4];
#pragma unroll
    for (int i = 0; i < 2; i++)
#pragma unroll
        for (int s = 0; s < 4; s++)
#pragma unroll
            for (int q = 0; q < 4; q++) outacc[i][s][q] = 0.f;

    const __half* Ax = xh + (size_t)m0 * D0;

    for (int j = 0; j < J_DOM; j++) {
        __syncthreads();   // protect bias + SMEM regions from previous j readers
        if (tid < 256) bias0[tid] = sb0[tid] + db0[j * H0 + tid];
        if (tid < 128) bias1[tid] = sb1[tid] + db1[j * H1 + tid];
        if (tid < 64)  bias2[tid] = sb2[tid] + db2[j * H2 + tid];

        // ================= phase A: L0  (K=512, N=256) =================
        const __half* W0p = w0 + (size_t)j * H0 * D0;

        load_tile<128>(Ax, D0, BUF + 0, tid);
        load_tile<256>(W0p, D0, BUF + 16384, tid);
        CP_COMMIT();

        float acc0[2][16][4];
#pragma unroll
        for (int i = 0; i < 2; i++)
#pragma unroll
            for (int s = 0; s < 16; s++)
#pragma unroll
                for (int q = 0; q < 4; q++) acc0[i][s][q] = 0.f;

        for (int c = 0; c < 8; c++) {
            if (c + 1 < 8) {
                uint32_t nb = BUF + ((c + 1) & 1) * 49152;
                int ko = (c + 1) * 64;
                load_tile<128>(Ax + ko, D0, nb, tid);
                load_tile<256>(W0p + ko, D0, nb + 16384, tid);
                CP_COMMIT();
                CP_WAIT(1);
            } else {
                CP_WAIT(0);
            }
            __syncthreads();
            uint32_t bu = BUF + (c & 1) * 49152;
            chunk_mma<8>(acc0, bu, bu + 16384, lane, wm, wnA);
            __syncthreads();
        }

        // preload W1 (W1S region disjoint from live data); overlaps h0 epilogue
        const __half* W1p = w1 + (size_t)j * H1 * H0;
        load_tile<128>(W1p, H0, W1S + 0, tid);
        CP_COMMIT();

        // h0 -> SMEM (fp16, 4 chunks x 16KB)
        epi_half<16>(acc0, bias0, H0S, lane, wm, wnA);
        __syncthreads();

        // ================= phase B: L1  (K=256, N=128) =================
        float acc1[2][8][4];
#pragma unroll
        for (int i = 0; i < 2; i++)
#pragma unroll
            for (int s = 0; s < 8; s++)
#pragma unroll
                for (int q = 0; q < 4; q++) acc1[i][s][q] = 0.f;

        for (int c = 0; c < 4; c++) {
            if (c + 1 < 4) {
                uint32_t nb = W1S + ((c + 1) & 1) * 16384;
                int ko = (c + 1) * 64;
                load_tile<128>(W1p + ko, H0, nb, tid);
                CP_COMMIT();
                CP_WAIT(1);
            } else {
                CP_WAIT(0);
            }
            __syncthreads();
            uint32_t au = H0S + c * 16384;
            uint32_t bu = W1S + (c & 1) * 16384;
            chunk_mma<4>(acc1, au, bu, lane, wm, wnB);
            __syncthreads();
        }

        // preload W2 (W2S dead since prior j phase C); overlaps h1 epilogue
        const __half* W2p = w2 + (size_t)j * H2 * H1;
#pragma unroll
        for (int c = 0; c < 2; c++)
            load_tile<64>(W2p + c * 64, H1, W2S + c * 8192, tid);
        CP_COMMIT();

        // h1 -> SMEM (fp16, 2 chunks x 16KB)
        epi_half<8>(acc1, bias1, H1S, lane, wm, wnB);
        CP_WAIT(0);
        __syncthreads();

        // ================= phase C: L2 (K=128, N=64) + mix =================
        float acc2[2][4][4];
#pragma unroll
        for (int i = 0; i < 2; i++)
#pragma unroll
            for (int s = 0; s < 4; s++)
#pragma unroll
                for (int q = 0; q < 4; q++) acc2[i][s][q] = 0.f;

#pragma unroll
        for (int c = 0; c < 2; c++) {
            uint32_t au = H1S + c * 16384;
            uint32_t bu = W2S + c * 8192;
            chunk_mma<2>(acc2, au, bu, lane, wm, wnC);
        }

        // mix-accumulate into persistent registers
#pragma unroll
        for (int i = 0; i < 2; i++) {
#pragma unroll
            for (int h = 0; h < 2; h++) {
                int row = wm + i * 16 + (lane >> 2) + h * 8;
                float iv = __ldg(ind + (size_t)(m0 + row) * J_DOM + j);
#pragma unroll
                for (int s = 0; s < 4; s++) {
                    int n = wnC + s * 8 + (lane & 3) * 2;
                    float v0 = fmaxf(acc2[i][s][2 * h + 0] + bias2[n], 0.f);
                    float v1 = fmaxf(acc2[i][s][2 * h + 1] + bias2[n + 1], 0.f);
                    outacc[i][s][2 * h + 0] = fmaf(iv, v0, outacc[i][s][2 * h + 0]);
                    outacc[i][s][2 * h + 1] = fmaf(iv, v1, outacc[i][s][2 * h + 1]);
                }
            }
        }
        // top-of-loop __syncthreads protects region reuse for next j
    }

    // final output write
#pragma unroll
    for (int i = 0; i < 2; i++) {
#pragma unroll
        for (int s = 0; s < 4; s++) {
            int n = wnC + s * 8 + (lane & 3) * 2;
#pragma unroll
            for (int h = 0; h < 2; h++) {
                int row = wm + i * 16 + (lane >> 2) + h * 8;
                *(float2*)(out + (size_t)(m0 + row) * H2 + n) =
                    make_float2(outacc[i][s][2 * h + 0], outacc[i][s][2 * h + 1]);
            }
        }
    }
}

// ---------------------------------------------------------------------------
extern "C" void kernel_launch(void* const* d_in, const int* in_sizes, int n_in,
                              void* d_out, int out_size) {
    const float* x   = (const float*)d_in[0];
    const float* ind = (const float*)d_in[1];
    const float* sk0 = (const float*)d_in[2];
    const float* sb0 = (const float*)d_in[3];
    const float* dk0 = (const float*)d_in[4];
    const float* db0 = (const float*)d_in[5];
    const float* sk1 = (const float*)d_in[6];
    const float* sb1 = (const float*)d_in[7];
    const float* dk1 = (const float*)d_in[8];
    const float* db1 = (const float*)d_in[9];
    const float* sk2 = (const float*)d_in[10];
    const float* sb2 = (const float*)d_in[11];
    const float* dk2 = (const float*)d_in[12];
    const float* db2 = (const float*)d_in[13];
    float* out = (float*)d_out;

    __half *xh, *w0, *w1, *w2;
    cudaGetSymbolAddress((void**)&xh, g_xh);
    cudaGetSymbolAddress((void**)&w0, g_w0);
    cudaGetSymbolAddress((void**)&w1, g_w1);
    cudaGetSymbolAddress((void**)&w2, g_w2);

    {
        size_t tx = (size_t)B_ROWS * D0;
        conv_half<<<(unsigned)((tx + 255) / 256), 256>>>(x, xh, tx);
        int t0 = J_DOM * D0 * H0, t1 = J_DOM * H0 * H1, t2 = J_DOM * H1 * H2;
        fuse_wT<<<(t0 + 255) / 256, 256>>>(sk0, dk0, w0, D0, H0, t0);
        fuse_wT<<<(t1 + 255) / 256, 256>>>(sk1, dk1, w1, H0, H1, t1);
        fuse_wT<<<(t2 + 255) / 256, 256>>>(sk2, dk2, w2, H1, H2, t2);
    }

    constexpr int SMEM = 182272;
    cudaFuncSetAttribute(star_fused, cudaFuncAttributeMaxDynamicSharedMemorySize, SMEM);

    star_fused<<<B_ROWS / 128, 256, SMEM>>>(
        xh, w0, w1, w2, sb0, db0, sb1, db1, sb2, db2, ind, out);
}

// round 15
// speedup vs baseline: 5.4905x; 1.5130x over previous
#include <cuda_runtime.h>
#include <cuda_fp16.h>
#include <cstdint>

// Problem constants
#define B_ROWS 65536
#define J_DOM  8
#define D0 512
#define H0 256
#define H1 128
#define H2 64

// ---------------------------------------------------------------------------
// baseline-PTX helpers (HMMA mma.sync + ldmatrix + cp.async only)
// ---------------------------------------------------------------------------
__device__ __forceinline__ uint32_t smem_to_u32(const void* p) {
    uint32_t a;
    asm("{ .reg .u64 t; cvta.to.shared.u64 t, %1; cvt.u32.u64 %0, t; }" : "=r"(a) : "l"(p));
    return a;
}
__device__ __forceinline__ void ldsm_x4(uint32_t* r, uint32_t addr) {
    asm volatile("ldmatrix.sync.aligned.m8n8.x4.shared.b16 {%0,%1,%2,%3}, [%4];"
                 : "=r"(r[0]), "=r"(r[1]), "=r"(r[2]), "=r"(r[3]) : "r"(addr));
}
__device__ __forceinline__ void mma16816(float* c, const uint32_t* a, const uint32_t* b) {
    asm volatile(
        "mma.sync.aligned.m16n8k16.row.col.f32.f16.f16.f32 "
        "{%0,%1,%2,%3}, {%4,%5,%6,%7}, {%8,%9}, {%0,%1,%2,%3};"
        : "+f"(c[0]), "+f"(c[1]), "+f"(c[2]), "+f"(c[3])
        : "r"(a[0]), "r"(a[1]), "r"(a[2]), "r"(a[3]), "r"(b[0]), "r"(b[1]));
}
__device__ __forceinline__ void cp16(uint32_t sm, const void* g) {
    asm volatile("cp.async.cg.shared.global [%0], [%1], 16;" :: "r"(sm), "l"(g));
}
#define CP_COMMIT() asm volatile("cp.async.commit_group;" ::: "memory")
#define CP_WAIT(n)  asm volatile("cp.async.wait_group %0;" :: "n"(n) : "memory")
__device__ __forceinline__ void sts32(uint32_t addr, uint32_t v) {
    asm volatile("st.shared.b32 [%0], %1;" :: "r"(addr), "r"(v));
}

// swizzled byte offset within a [rows x 64 halfs] tile (128B rows, 16B chunks)
__device__ __forceinline__ int swz(int row, int c) {
    return row * 128 + ((c ^ (row & 7)) << 4);
}

// ---------------------------------------------------------------------------
// Device scratch
// ---------------------------------------------------------------------------
__device__ __half g_xh[(size_t)B_ROWS * D0];      // 64 MB, fp16 x
__device__ __half g_w0[J_DOM * D0 * H0];          // [J][N][K] fp16
__device__ __half g_w1[J_DOM * H0 * H1];
__device__ __half g_w2[J_DOM * H1 * H2];

// ---------------------------------------------------------------------------
// single merged prologue kernel: x->fp16 + all three weight fuse/transposes
// (one kernel => star_fused is launch #2 of each replay => ncu -s 5 profiles it)
// ---------------------------------------------------------------------------
#define TX ((size_t)B_ROWS * D0)                 // 33554432
#define T0 (J_DOM * D0 * H0)                     // 1048576
#define T1 (J_DOM * H0 * H1)                     // 262144
#define T2 (J_DOM * H1 * H2)                     // 65536
__global__ void prologue(const float* __restrict__ x,
                         const float* __restrict__ sk0, const float* __restrict__ dk0,
                         const float* __restrict__ sk1, const float* __restrict__ dk1,
                         const float* __restrict__ sk2, const float* __restrict__ dk2,
                         __half* __restrict__ xh, __half* __restrict__ w0,
                         __half* __restrict__ w1, __half* __restrict__ w2) {
    size_t i = (size_t)blockIdx.x * blockDim.x + threadIdx.x;
    if (i < TX) {
        xh[i] = __float2half(x[i]);
        return;
    }
    size_t q = i - TX;
    if (q < T0) {
        int r = (int)(q % (D0 * H0)), j = (int)(q / (D0 * H0));
        int k = r / H0, n = r % H0;
        w0[(size_t)j * D0 * H0 + (size_t)n * D0 + k] = __float2half(sk0[r] * dk0[q]);
        return;
    }
    q -= T0;
    if (q < T1) {
        int r = (int)(q % (H0 * H1)), j = (int)(q / (H0 * H1));
        int k = r / H1, n = r % H1;
        w1[(size_t)j * H0 * H1 + (size_t)n * H0 + k] = __float2half(sk1[r] * dk1[q]);
        return;
    }
    q -= T1;
    if (q < T2) {
        int r = (int)(q % (H1 * H2)), j = (int)(q / (H1 * H2));
        int k = r / H2, n = r % H2;
        w2[(size_t)j * H1 * H2 + (size_t)n * H1 + k] = __float2half(sk2[r] * dk2[q]);
    }
}

// async tile loader: [ROWS x 64 halfs] K-major -> swizzled SMEM
template<int ROWS>
__device__ __forceinline__ void load_tile(const __half* __restrict__ src, int pitch,
                                          uint32_t dst, int tid) {
#pragma unroll
    for (int it = 0; it < ROWS / 32; it++) {
        int idx = tid + it * 256;
        int row = idx >> 3, c = idx & 7;
        cp16(dst + swz(row, c), src + (size_t)row * pitch + c * 8);
    }
}

// ---------------------------------------------------------------------------
// one K=64 chunk of single-pass fp16 MMAs:  acc += A @ B
// ---------------------------------------------------------------------------
template<int PAIRS>
__device__ __forceinline__ void chunk_mma(
    float (&acc)[2][2 * PAIRS][4],
    uint32_t aT, uint32_t bW,
    int lane, int wm, int wn)
{
#pragma unroll
    for (int ks = 0; ks < 4; ks++) {
        const int kc = ks * 2;
        uint32_t ah[2][4];
#pragma unroll
        for (int i = 0; i < 2; i++) {
            int row = wm + i * 16 + (lane & 15);
            int o = swz(row, kc + (lane >> 4));
            ldsm_x4(ah[i], aT + o);
        }
#pragma unroll
        for (int p = 0; p < PAIRS; p++) {
            int row = wn + p * 16 + ((lane >> 4) & 1) * 8 + (lane & 7);
            int o = swz(row, kc + ((lane >> 3) & 1));
            uint32_t bh[4];
            ldsm_x4(bh, bW + o);
#pragma unroll
            for (int i = 0; i < 2; i++) {
                mma16816(acc[i][2 * p + 0], ah[i], bh + 0);
                mma16816(acc[i][2 * p + 1], ah[i], bh + 2);
            }
        }
    }
}

// epilogue: bias + relu + fp16 round, C-frags -> swizzled SMEM A-layout
template<int NSUB>
__device__ __forceinline__ void epi_half(
    float (&acc)[2][NSUB][4], const float* __restrict__ bias,
    uint32_t dstBase, int lane, int wm, int wn)
{
#pragma unroll
    for (int i = 0; i < 2; i++) {
#pragma unroll
        for (int s = 0; s < NSUB; s++) {
            int n = wn + s * 8 + (lane & 3) * 2;
            float b0 = bias[n], b1 = bias[n + 1];
            int cA = n >> 6, cc = n & 63;
#pragma unroll
            for (int h = 0; h < 2; h++) {
                int row = wm + i * 16 + (lane >> 2) + h * 8;
                float v0 = fmaxf(acc[i][s][2 * h + 0] + b0, 0.f);
                float v1 = fmaxf(acc[i][s][2 * h + 1] + b1, 0.f);
                uint32_t hw = (uint32_t)__half_as_ushort(__float2half(v0)) |
                              ((uint32_t)__half_as_ushort(__float2half(v1)) << 16);
                uint32_t ad = dstBase + cA * 16384 + swz(row, cc >> 3) + (cc & 7) * 2;
                sts32(ad, hw);
            }
        }
    }
}

// ---------------------------------------------------------------------------
// fully fused STAR kernel with j-persistent x tile.
// SMEM map (byte offsets, total 231424):
//   [0,2048)            bias0/1/2
//   XS  = [2048,133120)   x: 8 chunks x 16K, loaded once at j=0, reused all j
//   W0B = [133120,198656)  W0 double stage 2 x 32K
//   H0S = [133120,198656)  h0: 4 chunks x 16K   (reuses W0B after phase A)
//   W2S = [133120,149504)  W2: 2 x 8K           (reuses H0S c0 after phase B c0)
//   W1S = [198656,231424)  W1 double stage 2 x 16K
//   H1S = [198656,231424)  h1: 2 chunks x 16K   (reuses W1S after phase B)
// ---------------------------------------------------------------------------
__global__ void __launch_bounds__(256, 1) star_fused(
    const __half* __restrict__ xh,
    const __half* __restrict__ w0, const __half* __restrict__ w1,
    const __half* __restrict__ w2,
    const float* __restrict__ sb0, const float* __restrict__ db0,
    const float* __restrict__ sb1, const float* __restrict__ db1,
    const float* __restrict__ sb2, const float* __restrict__ db2,
    const float* __restrict__ ind, float* __restrict__ out)
{
    extern __shared__ char smem[];
    const int tid = threadIdx.x, lane = tid & 31, wid = tid >> 5;
    const int m0 = blockIdx.x * 128;
    const int wm  = (wid & 3) * 32;
    const int wnA = (wid >> 2) * 128;
    const int wnB = (wid >> 2) * 64;
    const int wnC = (wid >> 2) * 32;

    float* bias0 = (float*)smem;
    float* bias1 = (float*)(smem + 1024);
    float* bias2 = (float*)(smem + 1536);
    const uint32_t sbase = smem_to_u32(smem);
    const uint32_t XS  = sbase + 2048;      // persistent x, 8 x 16K
    const uint32_t W0B = sbase + 133120;    // 2 stages x 32K
    const uint32_t H0S = sbase + 133120;
    const uint32_t W2S = sbase + 133120;
    const uint32_t W1S = sbase + 198656;    // 2 stages x 16K
    const uint32_t H1S = sbase + 198656;

    float outacc[2][4][4];
#pragma unroll
    for (int i = 0; i < 2; i++)
#pragma unroll
        for (int s = 0; s < 4; s++)
#pragma unroll
            for (int q = 0; q < 4; q++) outacc[i][s][q] = 0.f;

    const __half* Ax = xh + (size_t)m0 * D0;

    for (int j = 0; j < J_DOM; j++) {
        __syncthreads();   // protect bias + SMEM regions from previous j readers
        if (tid < 256) bias0[tid] = sb0[tid] + db0[j * H0 + tid];
        if (tid < 128) bias1[tid] = sb1[tid] + db1[j * H1 + tid];
        if (tid < 64)  bias2[tid] = sb2[tid] + db2[j * H2 + tid];

        // ================= phase A: L0  (K=512, N=256) =================
        const __half* W0p = w0 + (size_t)j * H0 * D0;

        if (j == 0) load_tile<128>(Ax, D0, XS, tid);   // x chunk 0, once ever
        load_tile<256>(W0p, D0, W0B, tid);
        CP_COMMIT();

        float acc0[2][16][4];
#pragma unroll
        for (int i = 0; i < 2; i++)
#pragma unroll
            for (int s = 0; s < 16; s++)
#pragma unroll
                for (int q = 0; q < 4; q++) acc0[i][s][q] = 0.f;

        for (int c = 0; c < 8; c++) {
            if (c + 1 < 8) {
                int ko = (c + 1) * 64;
                if (j == 0) load_tile<128>(Ax + ko, D0, XS + (c + 1) * 16384, tid);
                load_tile<256>(W0p + ko, D0, W0B + ((c + 1) & 1) * 32768, tid);
                CP_COMMIT();
                CP_WAIT(1);
            } else {
                CP_WAIT(0);
            }
            __syncthreads();
            chunk_mma<8>(acc0, XS + c * 16384, W0B + (c & 1) * 32768, lane, wm, wnA);
            __syncthreads();
        }

        // preload W1 (W1S region held dead h1 of prev j); overlaps h0 epilogue
        const __half* W1p = w1 + (size_t)j * H1 * H0;
        load_tile<128>(W1p, H0, W1S + 0, tid);
        CP_COMMIT();

        // h0 -> SMEM (fp16, 4 chunks x 16KB, reuses W0 stage block)
        epi_half<16>(acc0, bias0, H0S, lane, wm, wnA);
        __syncthreads();

        // ================= phase B: L1  (K=256, N=128) =================
        float acc1[2][8][4];
#pragma unroll
        for (int i = 0; i < 2; i++)
#pragma unroll
            for (int s = 0; s < 8; s++)
#pragma unroll
                for (int q = 0; q < 4; q++) acc1[i][s][q] = 0.f;

        for (int c = 0; c < 4; c++) {
            if (c + 1 < 4) {
                load_tile<128>(W1p + (c + 1) * 64, H0, W1S + ((c + 1) & 1) * 16384, tid);
                CP_COMMIT();
                CP_WAIT(1);
            } else {
                CP_WAIT(0);
            }
            __syncthreads();
            chunk_mma<4>(acc1, H0S + c * 16384, W1S + (c & 1) * 16384, lane, wm, wnB);
            __syncthreads();
        }

        // preload W2 (reuses H0S chunk-0 space, dead since phase B c=0)
        const __half* W2p = w2 + (size_t)j * H2 * H1;
#pragma unroll
        for (int c = 0; c < 2; c++)
            load_tile<64>(W2p + c * 64, H1, W2S + c * 8192, tid);
        CP_COMMIT();

        // h1 -> SMEM (fp16, 2 chunks x 16KB, reuses W1 stage block)
        epi_half<8>(acc1, bias1, H1S, lane, wm, wnB);
        CP_WAIT(0);
        __syncthreads();

        // ================= phase C: L2 (K=128, N=64) + mix =================
        float acc2[2][4][4];
#pragma unroll
        for (int i = 0; i < 2; i++)
#pragma unroll
            for (int s = 0; s < 4; s++)
#pragma unroll
                for (int q = 0; q < 4; q++) acc2[i][s][q] = 0.f;

#pragma unroll
        for (int c = 0; c < 2; c++)
            chunk_mma<2>(acc2, H1S + c * 16384, W2S + c * 8192, lane, wm, wnC);

        // mix-accumulate into persistent registers
#pragma unroll
        for (int i = 0; i < 2; i++) {
#pragma unroll
            for (int h = 0; h < 2; h++) {
                int row = wm + i * 16 + (lane >> 2) + h * 8;
                float iv = __ldg(ind + (size_t)(m0 + row) * J_DOM + j);
#pragma unroll
                for (int s = 0; s < 4; s++) {
                    int n = wnC + s * 8 + (lane & 3) * 2;
                    float v0 = fmaxf(acc2[i][s][2 * h + 0] + bias2[n], 0.f);
                    float v1 = fmaxf(acc2[i][s][2 * h + 1] + bias2[n + 1], 0.f);
                    outacc[i][s][2 * h + 0] = fmaf(iv, v0, outacc[i][s][2 * h + 0]);
                    outacc[i][s][2 * h + 1] = fmaf(iv, v1, outacc[i][s][2 * h + 1]);
                }
            }
        }
        // top-of-loop __syncthreads protects region reuse for next j
    }

    // final output write
#pragma unroll
    for (int i = 0; i < 2; i++) {
#pragma unroll
        for (int s = 0; s < 4; s++) {
            int n = wnC + s * 8 + (lane & 3) * 2;
#pragma unroll
            for (int h = 0; h < 2; h++) {
                int row = wm + i * 16 + (lane >> 2) + h * 8;
                *(float2*)(out + (size_t)(m0 + row) * H2 + n) =
                    make_float2(outacc[i][s][2 * h + 0], outacc[i][s][2 * h + 1]);
            }
        }
    }
}

// ---------------------------------------------------------------------------
extern "C" void kernel_launch(void* const* d_in, const int* in_sizes, int n_in,
                              void* d_out, int out_size) {
    const float* x   = (const float*)d_in[0];
    const float* ind = (const float*)d_in[1];
    const float* sk0 = (const float*)d_in[2];
    const float* sb0 = (const float*)d_in[3];
    const float* dk0 = (const float*)d_in[4];
    const float* db0 = (const float*)d_in[5];
    const float* sk1 = (const float*)d_in[6];
    const float* sb1 = (const float*)d_in[7];
    const float* dk1 = (const float*)d_in[8];
    const float* db1 = (const float*)d_in[9];
    const float* sk2 = (const float*)d_in[10];
    const float* sb2 = (const float*)d_in[11];
    const float* dk2 = (const float*)d_in[12];
    const float* db2 = (const float*)d_in[13];
    float* out = (float*)d_out;

    __half *xh, *w0, *w1, *w2;
    cudaGetSymbolAddress((void**)&xh, g_xh);
    cudaGetSymbolAddress((void**)&w0, g_w0);
    cudaGetSymbolAddress((void**)&w1, g_w1);
    cudaGetSymbolAddress((void**)&w2, g_w2);

    {
        size_t total = TX + T0 + T1 + T2;
        prologue<<<(unsigned)((total + 255) / 256), 256>>>(
            x, sk0, dk0, sk1, dk1, sk2, dk2, xh, w0, w1, w2);
    }

    constexpr int SMEM = 231424;
    cudaFuncSetAttribute(star_fused, cudaFuncAttributeMaxDynamicSharedMemorySize, SMEM);

    star_fused<<<B_ROWS / 128, 256, SMEM>>>(
        xh, w0, w1, w2, sb0, db0, sb1, db1, sb2, db2, ind, out);
}